// round 2
// baseline (speedup 1.0000x reference)
#include <cuda_runtime.h>
#include <math.h>

// Problem constants
#define BB 4
#define HH 64
#define WW 64
#define DD 256
#define NH 8
#define DK 32
#define DV 32
#define HW 4096      // H*W
#define P2 1024      // pooled pixels (H/2 * W/2)

// Scratch (device globals; no allocation allowed)
__device__ float g_q[BB * NH * P2 * DK];   //  4 MB  [b][n][p][k]
__device__ float g_k[BB * NH * HW * DK];   // 16 MB  [b][n][i][k]
__device__ float g_v[BB * NH * HW * DV];   // 16 MB  [b][n][i][v]

// ---------------------------------------------------------------------------
// Projection GEMM: C[M,256] = A[M,256] @ W[256,256] + bias, with per-mode
// input transform (maxpool for Q) and epilogue (scale for Q, swish for V),
// scattered into head-major scratch layout.
// MODE 0: Q (pooled input, M=4096, *1/sqrt(32))
// MODE 1: K (M=16384)
// MODE 2: V (M=16384, swish)
// Block tile 64x64, K-chunk 16, 256 threads, 4x4 register tile.
// ---------------------------------------------------------------------------
template <int MODE>
__global__ __launch_bounds__(256)
void proj_kernel(const float* __restrict__ A,
                 const float* __restrict__ Wm,
                 const float* __restrict__ bias)
{
    __shared__ float As[16][68];   // [k][m], pad 4 to keep 16B alignment
    __shared__ float Bs[16][68];   // [k][n]

    const int m0  = blockIdx.y << 6;
    const int n0  = blockIdx.x << 6;
    const int tid = threadIdx.x;
    const int tx  = tid & 15;
    const int ty  = tid >> 4;

    // A-tile loader mapping: each thread loads one float4
    const int am = tid >> 2;            // 0..63 (row within tile)
    const int ak = (tid & 3) << 2;      // 0,4,8,12 (k within chunk)
    // B-tile loader mapping
    const int bk = tid >> 4;            // 0..15
    const int bn = (tid & 15) << 2;     // 0..60

    const int arow = m0 + am;
    int abase;
    if (MODE == 0) {
        const int b  = arow >> 10;
        const int l  = arow & 1023;
        const int h2 = l >> 5;
        const int w2 = l & 31;
        abase = ((b * HH + 2 * h2) * WW + 2 * w2) * DD;
    } else {
        abase = arow * DD;
    }

    float acc[4][4];
#pragma unroll
    for (int i = 0; i < 4; i++)
#pragma unroll
        for (int j = 0; j < 4; j++) acc[i][j] = 0.0f;

    for (int k0 = 0; k0 < DD; k0 += 16) {
        // ---- load A tile (with fused 2x2 maxpool for MODE 0) ----
        float4 va;
        if (MODE == 0) {
            const float* p00 = A + abase + k0 + ak;
            float4 v0 = *(const float4*)(p00);
            float4 v1 = *(const float4*)(p00 + DD);
            float4 v2 = *(const float4*)(p00 + WW * DD);
            float4 v3 = *(const float4*)(p00 + WW * DD + DD);
            va.x = fmaxf(fmaxf(v0.x, v1.x), fmaxf(v2.x, v3.x));
            va.y = fmaxf(fmaxf(v0.y, v1.y), fmaxf(v2.y, v3.y));
            va.z = fmaxf(fmaxf(v0.z, v1.z), fmaxf(v2.z, v3.z));
            va.w = fmaxf(fmaxf(v0.w, v1.w), fmaxf(v2.w, v3.w));
        } else {
            va = *(const float4*)(A + abase + k0 + ak);
        }
        As[ak + 0][am] = va.x;
        As[ak + 1][am] = va.y;
        As[ak + 2][am] = va.z;
        As[ak + 3][am] = va.w;

        // ---- load B tile ----
        float4 vb = *(const float4*)(Wm + (k0 + bk) * 256 + n0 + bn);
        *(float4*)&Bs[bk][bn] = vb;

        __syncthreads();

#pragma unroll
        for (int kk = 0; kk < 16; kk++) {
            float a[4], b2[4];
#pragma unroll
            for (int i = 0; i < 4; i++) a[i] = As[kk][(ty << 2) + i];
#pragma unroll
            for (int j = 0; j < 4; j++) b2[j] = Bs[kk][(tx << 2) + j];
#pragma unroll
            for (int i = 0; i < 4; i++)
#pragma unroll
                for (int j = 0; j < 4; j++)
                    acc[i][j] = fmaf(a[i], b2[j], acc[i][j]);
        }
        __syncthreads();
    }

    // ---- epilogue: bias, activation/scale, scatter to head-major layout ----
#pragma unroll
    for (int i = 0; i < 4; i++) {
        const int r = m0 + (ty << 2) + i;
#pragma unroll
        for (int j = 0; j < 4; j++) {
            const int c   = n0 + (tx << 2) + j;
            float val     = acc[i][j] + bias[c];
            const int n   = c >> 5;
            const int kk2 = c & 31;
            if (MODE == 0) {
                val *= 0.17677669529663687f;           // 1/sqrt(32)
                const int b = r >> 10, p = r & 1023;
                g_q[(((b * NH + n) * P2) + p) * DK + kk2] = val;
            } else if (MODE == 1) {
                const int b = r >> 12, ii = r & 4095;
                g_k[(((b * NH + n) * HW) + ii) * DK + kk2] = val;
            } else {
                val = val / (1.0f + expf(-val));       // swish
                const int b = r >> 12, ii = r & 4095;
                g_v[(((b * NH + n) * HW) + ii) * DV + kk2] = val;
            }
        }
    }
}

// ---------------------------------------------------------------------------
// Flash attention: per (b, n), Q[1024,32] x K[4096,32] -> softmax -> x V[4096,32]
// 1 thread = 1 query (Q + accumulator in registers), K/V streamed through smem
// in 128-key chunks. Online softmax with rescale only on max update.
// ---------------------------------------------------------------------------
__global__ __launch_bounds__(128)
void attn_kernel(float* __restrict__ out)
{
    __shared__ float Ks[128][DK];
    __shared__ float Vs[128][DV];

    const int tid = threadIdx.x;
    const int q   = blockIdx.x * 128 + tid;          // 0..1023
    const int n   = blockIdx.y;
    const int b   = blockIdx.z;
    const int bn  = b * NH + n;

    // Q row into registers
    float Q[32];
    const float4* qp = (const float4*)(g_q + (bn * P2 + q) * DK);
#pragma unroll
    for (int i = 0; i < 8; i++) {
        float4 t = qp[i];
        Q[4 * i + 0] = t.x; Q[4 * i + 1] = t.y;
        Q[4 * i + 2] = t.z; Q[4 * i + 3] = t.w;
    }

    float m = -INFINITY, l = 0.0f;
    float acc[32];
#pragma unroll
    for (int i = 0; i < 32; i++) acc[i] = 0.0f;

    const float4* kp = (const float4*)(g_k + bn * HW * DK);
    const float4* vp = (const float4*)(g_v + bn * HW * DV);

    for (int j0 = 0; j0 < HW; j0 += 128) {
        __syncthreads();
#pragma unroll
        for (int t = 0; t < 8; t++) {
            const int idx = t * 128 + tid;           // 0..1023 float4s
            ((float4*)Ks)[idx] = kp[j0 * 8 + idx];
            ((float4*)Vs)[idx] = vp[j0 * 8 + idx];
        }
        __syncthreads();

#pragma unroll 4
        for (int j = 0; j < 128; j++) {
            const float* kr = Ks[j];
            float s = 0.0f;
#pragma unroll
            for (int k = 0; k < 32; k++) s = fmaf(Q[k], kr[k], s);

            float p;
            if (s > m) {
                const float corr = __expf(m - s);    // exp(-inf)=0 on first key
                m = s;
                l *= corr;
#pragma unroll
                for (int v2 = 0; v2 < 32; v2++) acc[v2] *= corr;
                p = 1.0f;
            } else {
                p = __expf(s - m);
            }
            l += p;

            const float* vr = Vs[j];
#pragma unroll
            for (int v2 = 0; v2 < 32; v2++) acc[v2] = fmaf(p, vr[v2], acc[v2]);
        }
    }

    const float inv = 1.0f / l;
    // out[b][p][n*32 + v]
    float4* op = (float4*)(out + (b * P2 + q) * 256 + n * DV);
#pragma unroll
    for (int i = 0; i < 8; i++) {
        float4 t;
        t.x = acc[4 * i + 0] * inv; t.y = acc[4 * i + 1] * inv;
        t.z = acc[4 * i + 2] * inv; t.w = acc[4 * i + 3] * inv;
        op[i] = t;
    }
}

// ---------------------------------------------------------------------------
extern "C" void kernel_launch(void* const* d_in, const int* in_sizes, int n_in,
                              void* d_out, int out_size)
{
    const float* blob = (const float*)d_in[0];
    const float* wq   = (const float*)d_in[1];
    const float* bq   = (const float*)d_in[2];
    const float* wk   = (const float*)d_in[3];
    const float* bk   = (const float*)d_in[4];
    const float* wv   = (const float*)d_in[5];
    const float* bv   = (const float*)d_in[6];
    float* out        = (float*)d_out;

    // Projections (independent, serialized on default stream — fine)
    proj_kernel<0><<<dim3(4, 64),  256>>>(blob, wq, bq);   // Q: M=4096
    proj_kernel<1><<<dim3(4, 256), 256>>>(blob, wk, bk);   // K: M=16384
    proj_kernel<2><<<dim3(4, 256), 256>>>(blob, wv, bv);   // V: M=16384

    // Attention: grid (query-tile, head, batch)
    attn_kernel<<<dim3(8, NH, BB), 128>>>(out);
}

// round 3
// speedup vs baseline: 2.0940x; 2.0940x over previous
#include <cuda_runtime.h>
#include <math.h>
#include <stdint.h>

// Problem constants
#define BB 4
#define HH 64
#define WW 64
#define DD 256
#define NH 8
#define DK 32
#define DV 32
#define HW 4096      // H*W
#define P2 1024      // pooled pixels

// Scratch (device globals; no allocation allowed)
__device__ float g_q[BB * NH * P2 * DK];   //  4 MB  [b][n][p][k]
__device__ float g_k[BB * NH * HW * DK];   // 16 MB  [b][n][i][k]
__device__ float g_v[BB * NH * HW * DV];   // 16 MB  [b][n][i][v]

// ---------------------------------------------------------------------------
// Projection GEMM (unchanged from R1): C = A @ W + bias, fused maxpool (Q),
// scale (Q), swish (V); scatter to head-major scratch.
// ---------------------------------------------------------------------------
template <int MODE>
__global__ __launch_bounds__(256)
void proj_kernel(const float* __restrict__ A,
                 const float* __restrict__ Wm,
                 const float* __restrict__ bias)
{
    __shared__ float As[16][68];
    __shared__ float Bs[16][68];

    const int m0  = blockIdx.y << 6;
    const int n0  = blockIdx.x << 6;
    const int tid = threadIdx.x;
    const int tx  = tid & 15;
    const int ty  = tid >> 4;

    const int am = tid >> 2;
    const int ak = (tid & 3) << 2;
    const int bk = tid >> 4;
    const int bn = (tid & 15) << 2;

    const int arow = m0 + am;
    int abase;
    if (MODE == 0) {
        const int b  = arow >> 10;
        const int l  = arow & 1023;
        const int h2 = l >> 5;
        const int w2 = l & 31;
        abase = ((b * HH + 2 * h2) * WW + 2 * w2) * DD;
    } else {
        abase = arow * DD;
    }

    float acc[4][4];
#pragma unroll
    for (int i = 0; i < 4; i++)
#pragma unroll
        for (int j = 0; j < 4; j++) acc[i][j] = 0.0f;

    for (int k0 = 0; k0 < DD; k0 += 16) {
        float4 va;
        if (MODE == 0) {
            const float* p00 = A + abase + k0 + ak;
            float4 v0 = *(const float4*)(p00);
            float4 v1 = *(const float4*)(p00 + DD);
            float4 v2 = *(const float4*)(p00 + WW * DD);
            float4 v3 = *(const float4*)(p00 + WW * DD + DD);
            va.x = fmaxf(fmaxf(v0.x, v1.x), fmaxf(v2.x, v3.x));
            va.y = fmaxf(fmaxf(v0.y, v1.y), fmaxf(v2.y, v3.y));
            va.z = fmaxf(fmaxf(v0.z, v1.z), fmaxf(v2.z, v3.z));
            va.w = fmaxf(fmaxf(v0.w, v1.w), fmaxf(v2.w, v3.w));
        } else {
            va = *(const float4*)(A + abase + k0 + ak);
        }
        As[ak + 0][am] = va.x;
        As[ak + 1][am] = va.y;
        As[ak + 2][am] = va.z;
        As[ak + 3][am] = va.w;

        float4 vb = *(const float4*)(Wm + (k0 + bk) * 256 + n0 + bn);
        *(float4*)&Bs[bk][bn] = vb;

        __syncthreads();

#pragma unroll
        for (int kk = 0; kk < 16; kk++) {
            float a[4], b2[4];
#pragma unroll
            for (int i = 0; i < 4; i++) a[i] = As[kk][(ty << 2) + i];
#pragma unroll
            for (int j = 0; j < 4; j++) b2[j] = Bs[kk][(tx << 2) + j];
#pragma unroll
            for (int i = 0; i < 4; i++)
#pragma unroll
                for (int j = 0; j < 4; j++)
                    acc[i][j] = fmaf(a[i], b2[j], acc[i][j]);
        }
        __syncthreads();
    }

#pragma unroll
    for (int i = 0; i < 4; i++) {
        const int r = m0 + (ty << 2) + i;
#pragma unroll
        for (int j = 0; j < 4; j++) {
            const int c   = n0 + (tx << 2) + j;
            float val     = acc[i][j] + bias[c];
            const int n   = c >> 5;
            const int kk2 = c & 31;
            if (MODE == 0) {
                val *= 0.17677669529663687f;
                const int b = r >> 10, p = r & 1023;
                g_q[(((b * NH + n) * P2) + p) * DK + kk2] = val;
            } else if (MODE == 1) {
                const int b = r >> 12, ii = r & 4095;
                g_k[(((b * NH + n) * HW) + ii) * DK + kk2] = val;
            } else {
                val = val / (1.0f + expf(-val));
                const int b = r >> 12, ii = r & 4095;
                g_v[(((b * NH + n) * HW) + ii) * DV + kk2] = val;
            }
        }
    }
}

// ---------------------------------------------------------------------------
// tf32 tensor-core flash attention.
// Block: 128 threads (4 warps), 64 queries; warp w owns query rows [16w,16w+16).
// Key loop: 64 keys/iter through smem. Q fragments in registers for all iters.
// S = Q K^T via mma.m16n8k8 tf32; online softmax on fragments (quad shuffles);
// P staged through per-warp smem; O += P V via mma.m16n8k8 tf32.
// ---------------------------------------------------------------------------
__device__ __forceinline__ uint32_t f2tf32(float f) {
    uint32_t u;
    asm("cvt.rna.tf32.f32 %0, %1;" : "=r"(u) : "f"(f));
    return u;
}

__device__ __forceinline__ void mma_tf32(float& d0, float& d1, float& d2, float& d3,
                                         uint32_t a0, uint32_t a1, uint32_t a2, uint32_t a3,
                                         uint32_t b0, uint32_t b1) {
    asm volatile(
        "mma.sync.aligned.m16n8k8.row.col.f32.tf32.tf32.f32 "
        "{%0,%1,%2,%3}, {%4,%5,%6,%7}, {%8,%9}, {%0,%1,%2,%3};\n"
        : "+f"(d0), "+f"(d1), "+f"(d2), "+f"(d3)
        : "r"(a0), "r"(a1), "r"(a2), "r"(a3), "r"(b0), "r"(b1));
}

__global__ __launch_bounds__(128)
void attn_tc_kernel(float* __restrict__ out)
{
    __shared__ float Qs[64][36];          // padded: stride 36 -> conflict-free frags
    __shared__ float Ks[64][36];
    __shared__ float Vs[64][36];
    __shared__ float Ps[4][16][68];       // per-warp P tile 16x64, stride 68

    const int tid  = threadIdx.x;
    const int w    = tid >> 5;
    const int lane = tid & 31;
    const int g    = lane >> 2;           // groupID (row within 8)
    const int tig  = lane & 3;            // thread-in-group

    const int qt = blockIdx.x;            // 0..15 query tile
    const int n  = blockIdx.y;
    const int b  = blockIdx.z;
    const int bn = b * NH + n;

    const float* qglob = g_q + (bn * P2 + qt * 64) * DK;
    const float* kglob = g_k + (size_t)bn * HW * DK;
    const float* vglob = g_v + (size_t)bn * HW * DV;

    // ---- stage Q tile (rounded to tf32) ----
    for (int i = tid; i < 512; i += 128) {        // 512 float4s
        const int row = i >> 3;
        const int c   = (i & 7) << 2;
        float4 v = *(const float4*)(qglob + row * 32 + c);
        Qs[row][c + 0] = __uint_as_float(f2tf32(v.x));
        Qs[row][c + 1] = __uint_as_float(f2tf32(v.y));
        Qs[row][c + 2] = __uint_as_float(f2tf32(v.z));
        Qs[row][c + 3] = __uint_as_float(f2tf32(v.w));
    }
    __syncthreads();

    // ---- Q fragments in registers: Qf[kc][0..3] (a0..a3 for m16k8 chunk kc) ----
    uint32_t Qf[4][4];
    const int r0 = w * 16 + g;
#pragma unroll
    for (int kc = 0; kc < 4; kc++) {
        Qf[kc][0] = __float_as_uint(Qs[r0    ][kc * 8 + tig    ]);
        Qf[kc][1] = __float_as_uint(Qs[r0 + 8][kc * 8 + tig    ]);
        Qf[kc][2] = __float_as_uint(Qs[r0    ][kc * 8 + tig + 4]);
        Qf[kc][3] = __float_as_uint(Qs[r0 + 8][kc * 8 + tig + 4]);
    }

    float m0 = -INFINITY, m1 = -INFINITY, l0 = 0.0f, l1 = 0.0f;
    float oacc[4][4];
#pragma unroll
    for (int i = 0; i < 4; i++)
#pragma unroll
        for (int j = 0; j < 4; j++) oacc[i][j] = 0.0f;

    for (int j0 = 0; j0 < HW; j0 += 64) {
        __syncthreads();
        // ---- stage K/V tiles (rounded to tf32) ----
        for (int i = tid; i < 512; i += 128) {
            const int row = i >> 3;
            const int c   = (i & 7) << 2;
            float4 kv = *(const float4*)(kglob + (j0 + row) * 32 + c);
            float4 vv = *(const float4*)(vglob + (j0 + row) * 32 + c);
            Ks[row][c + 0] = __uint_as_float(f2tf32(kv.x));
            Ks[row][c + 1] = __uint_as_float(f2tf32(kv.y));
            Ks[row][c + 2] = __uint_as_float(f2tf32(kv.z));
            Ks[row][c + 3] = __uint_as_float(f2tf32(kv.w));
            Vs[row][c + 0] = __uint_as_float(f2tf32(vv.x));
            Vs[row][c + 1] = __uint_as_float(f2tf32(vv.y));
            Vs[row][c + 2] = __uint_as_float(f2tf32(vv.z));
            Vs[row][c + 3] = __uint_as_float(f2tf32(vv.w));
        }
        __syncthreads();

        // ---- S = Q K^T : 16x64 per warp, 8 n-tiles of 8 keys ----
        float sacc[8][4];
#pragma unroll
        for (int nt = 0; nt < 8; nt++)
#pragma unroll
            for (int j = 0; j < 4; j++) sacc[nt][j] = 0.0f;

#pragma unroll
        for (int kc = 0; kc < 4; kc++) {
#pragma unroll
            for (int nt = 0; nt < 8; nt++) {
                const uint32_t b0 = __float_as_uint(Ks[nt * 8 + g][kc * 8 + tig    ]);
                const uint32_t b1 = __float_as_uint(Ks[nt * 8 + g][kc * 8 + tig + 4]);
                mma_tf32(sacc[nt][0], sacc[nt][1], sacc[nt][2], sacc[nt][3],
                         Qf[kc][0], Qf[kc][1], Qf[kc][2], Qf[kc][3], b0, b1);
            }
        }

        // ---- online softmax on fragments ----
        float mx0 = -INFINITY, mx1 = -INFINITY;
#pragma unroll
        for (int nt = 0; nt < 8; nt++) {
            mx0 = fmaxf(mx0, fmaxf(sacc[nt][0], sacc[nt][1]));
            mx1 = fmaxf(mx1, fmaxf(sacc[nt][2], sacc[nt][3]));
        }
        mx0 = fmaxf(mx0, __shfl_xor_sync(0xffffffffu, mx0, 1));
        mx0 = fmaxf(mx0, __shfl_xor_sync(0xffffffffu, mx0, 2));
        mx1 = fmaxf(mx1, __shfl_xor_sync(0xffffffffu, mx1, 1));
        mx1 = fmaxf(mx1, __shfl_xor_sync(0xffffffffu, mx1, 2));

        const float nm0 = fmaxf(m0, mx0);
        const float nm1 = fmaxf(m1, mx1);
        const float sc0 = __expf(m0 - nm0);   // exp(-inf)=0 on first tile
        const float sc1 = __expf(m1 - nm1);
        m0 = nm0; m1 = nm1;

        float rs0 = 0.0f, rs1 = 0.0f;
#pragma unroll
        for (int nt = 0; nt < 8; nt++) {
            const float p0 = __expf(sacc[nt][0] - nm0);
            const float p1 = __expf(sacc[nt][1] - nm0);
            const float p2 = __expf(sacc[nt][2] - nm1);
            const float p3 = __expf(sacc[nt][3] - nm1);
            rs0 += p0 + p1;
            rs1 += p2 + p3;
            *(float2*)&Ps[w][g    ][nt * 8 + 2 * tig] = make_float2(p0, p1);
            *(float2*)&Ps[w][g + 8][nt * 8 + 2 * tig] = make_float2(p2, p3);
        }
        rs0 += __shfl_xor_sync(0xffffffffu, rs0, 1);
        rs0 += __shfl_xor_sync(0xffffffffu, rs0, 2);
        rs1 += __shfl_xor_sync(0xffffffffu, rs1, 1);
        rs1 += __shfl_xor_sync(0xffffffffu, rs1, 2);
        l0 = l0 * sc0 + rs0;
        l1 = l1 * sc1 + rs1;

#pragma unroll
        for (int nt = 0; nt < 4; nt++) {
            oacc[nt][0] *= sc0; oacc[nt][1] *= sc0;
            oacc[nt][2] *= sc1; oacc[nt][3] *= sc1;
        }
        __syncwarp();

        // ---- O += P V : A-frags from Ps, B-frags from Vs ----
#pragma unroll
        for (int kc = 0; kc < 8; kc++) {
            const uint32_t a0 = __float_as_uint(Ps[w][g    ][kc * 8 + tig    ]);
            const uint32_t a1 = __float_as_uint(Ps[w][g + 8][kc * 8 + tig    ]);
            const uint32_t a2 = __float_as_uint(Ps[w][g    ][kc * 8 + tig + 4]);
            const uint32_t a3 = __float_as_uint(Ps[w][g + 8][kc * 8 + tig + 4]);
#pragma unroll
            for (int nt = 0; nt < 4; nt++) {
                const uint32_t b0 = __float_as_uint(Vs[kc * 8 + tig    ][nt * 8 + g]);
                const uint32_t b1 = __float_as_uint(Vs[kc * 8 + tig + 4][nt * 8 + g]);
                mma_tf32(oacc[nt][0], oacc[nt][1], oacc[nt][2], oacc[nt][3],
                         a0, a1, a2, a3, b0, b1);
            }
        }
        __syncwarp();   // protect Ps before next iteration's stores
    }

    // ---- epilogue: normalize, write out[b][q][n*32 + dv] ----
    const float i0 = 1.0f / l0;
    const float i1 = 1.0f / l1;
    const int q0 = qt * 64 + w * 16 + g;
    float* op0 = out + ((size_t)(b * P2 + q0    ) * 256) + n * DV;
    float* op1 = out + ((size_t)(b * P2 + q0 + 8) * 256) + n * DV;
#pragma unroll
    for (int nt = 0; nt < 4; nt++) {
        *(float2*)(op0 + nt * 8 + 2 * tig) = make_float2(oacc[nt][0] * i0, oacc[nt][1] * i0);
        *(float2*)(op1 + nt * 8 + 2 * tig) = make_float2(oacc[nt][2] * i1, oacc[nt][3] * i1);
    }
}

// ---------------------------------------------------------------------------
extern "C" void kernel_launch(void* const* d_in, const int* in_sizes, int n_in,
                              void* d_out, int out_size)
{
    const float* blob = (const float*)d_in[0];
    const float* wq   = (const float*)d_in[1];
    const float* bq   = (const float*)d_in[2];
    const float* wk   = (const float*)d_in[3];
    const float* bk   = (const float*)d_in[4];
    const float* wv   = (const float*)d_in[5];
    const float* bv   = (const float*)d_in[6];
    float* out        = (float*)d_out;

    proj_kernel<0><<<dim3(4, 64),  256>>>(blob, wq, bq);   // Q
    proj_kernel<1><<<dim3(4, 256), 256>>>(blob, wk, bk);   // K
    proj_kernel<2><<<dim3(4, 256), 256>>>(blob, wv, bv);   // V

    attn_tc_kernel<<<dim3(16, NH, BB), 128>>>(out);
}

// round 4
// speedup vs baseline: 4.0688x; 1.9430x over previous
#include <cuda_runtime.h>
#include <cuda_fp16.h>
#include <math.h>
#include <stdint.h>

// Problem constants
#define BB 4
#define HH 64
#define WW 64
#define DD 256
#define NH 8
#define DK 32
#define DV 32
#define HW 4096      // H*W
#define P2 1024      // pooled pixels

// Scratch (device globals)
__device__ float  g_q[BB * NH * P2 * DK];   //  4 MB [bn][p][k]   tf32-rounded
__device__ float  g_k[BB * NH * HW * DK];   // 16 MB [bn][i][k]   tf32-rounded
__device__ __half g_v[BB * NH * DV * HW];   //  8 MB [bn][d][i]   f16, TRANSPOSED

// ---------------------------------------------------------------------------
// helpers
// ---------------------------------------------------------------------------
__device__ __forceinline__ uint32_t f2tf32(float f) {
    uint32_t u;
    asm("cvt.rna.tf32.f32 %0, %1;" : "=r"(u) : "f"(f));
    return u;
}

__device__ __forceinline__ void mma_tf32(float& d0, float& d1, float& d2, float& d3,
                                         uint32_t a0, uint32_t a1, uint32_t a2, uint32_t a3,
                                         uint32_t b0, uint32_t b1) {
    asm volatile(
        "mma.sync.aligned.m16n8k8.row.col.f32.tf32.tf32.f32 "
        "{%0,%1,%2,%3}, {%4,%5,%6,%7}, {%8,%9}, {%0,%1,%2,%3};\n"
        : "+f"(d0), "+f"(d1), "+f"(d2), "+f"(d3)
        : "r"(a0), "r"(a1), "r"(a2), "r"(a3), "r"(b0), "r"(b1));
}

__device__ __forceinline__ void mma_f16(float& d0, float& d1, float& d2, float& d3,
                                        uint32_t a0, uint32_t a1, uint32_t a2, uint32_t a3,
                                        uint32_t b0, uint32_t b1) {
    asm volatile(
        "mma.sync.aligned.m16n8k16.row.col.f32.f16.f16.f32 "
        "{%0,%1,%2,%3}, {%4,%5,%6,%7}, {%8,%9}, {%0,%1,%2,%3};\n"
        : "+f"(d0), "+f"(d1), "+f"(d2), "+f"(d3)
        : "r"(a0), "r"(a1), "r"(a2), "r"(a3), "r"(b0), "r"(b1));
}

__device__ __forceinline__ void cpa16(uint32_t s, const void* g) {
    asm volatile("cp.async.ca.shared.global [%0], [%1], 16;\n" :: "r"(s), "l"(g));
}
__device__ __forceinline__ void cpa_commit() {
    asm volatile("cp.async.commit_group;\n");
}
template <int N>
__device__ __forceinline__ void cpa_wait() {
    asm volatile("cp.async.wait_group %0;\n" :: "n"(N));
}

// ---------------------------------------------------------------------------
// tf32 tensor-core projection: C[M,256] = A[M,256] @ W[256,256] + bias
// MODE 0: Q (fused 2x2 maxpool input, *1/sqrt(32), tf32-round, -> g_q)
// MODE 1: K (tf32-round -> g_k)
// MODE 2: V (swish, f16, TRANSPOSED -> g_v[bn][d][i])
// Block: 128 threads (4 warps). Tile: M=128 (warp: 32 rows), N=64, k-step 16.
// ---------------------------------------------------------------------------
template <int MODE>
__global__ __launch_bounds__(128)
void proj_tc_kernel(const float* __restrict__ A,
                    const float* __restrict__ Wm,
                    const float* __restrict__ bias)
{
    __shared__ float As[128][20];   // [m][k16], pad 4
    __shared__ float Ws[16][68];    // [k16][n64], pad 4

    const int tid  = threadIdx.x;
    const int w    = tid >> 5;
    const int lane = tid & 31;
    const int g    = lane >> 2;
    const int tig  = lane & 3;

    const int n0 = blockIdx.x << 6;
    const int m0 = blockIdx.y << 7;

    float acc[2][8][4];   // [m-tile][n-tile][c-regs]
#pragma unroll
    for (int t = 0; t < 2; t++)
#pragma unroll
        for (int nt = 0; nt < 8; nt++)
#pragma unroll
            for (int j = 0; j < 4; j++) acc[t][nt][j] = 0.0f;

    for (int k0 = 0; k0 < DD; k0 += 16) {
        // ---- stage A tile: 128 rows x 16 floats = 512 float4 ----
#pragma unroll
        for (int t = 0; t < 4; t++) {
            const int i   = tid + 128 * t;
            const int row = i >> 2;
            const int c4  = (i & 3) << 2;
            const int r   = m0 + row;
            float4 va;
            if (MODE == 0) {
                const int b  = r >> 10;
                const int l  = r & 1023;
                const int h2 = l >> 5;
                const int w2 = l & 31;
                const float* p00 = A + ((b * HH + 2 * h2) * WW + 2 * w2) * DD + k0 + c4;
                float4 v0 = *(const float4*)(p00);
                float4 v1 = *(const float4*)(p00 + DD);
                float4 v2 = *(const float4*)(p00 + WW * DD);
                float4 v3 = *(const float4*)(p00 + WW * DD + DD);
                va.x = fmaxf(fmaxf(v0.x, v1.x), fmaxf(v2.x, v3.x));
                va.y = fmaxf(fmaxf(v0.y, v1.y), fmaxf(v2.y, v3.y));
                va.z = fmaxf(fmaxf(v0.z, v1.z), fmaxf(v2.z, v3.z));
                va.w = fmaxf(fmaxf(v0.w, v1.w), fmaxf(v2.w, v3.w));
            } else {
                va = *(const float4*)(A + (size_t)r * DD + k0 + c4);
            }
            As[row][c4 + 0] = __uint_as_float(f2tf32(va.x));
            As[row][c4 + 1] = __uint_as_float(f2tf32(va.y));
            As[row][c4 + 2] = __uint_as_float(f2tf32(va.z));
            As[row][c4 + 3] = __uint_as_float(f2tf32(va.w));
        }
        // ---- stage W tile: 16 k-rows x 64 = 256 float4 ----
#pragma unroll
        for (int t = 0; t < 2; t++) {
            const int i  = tid + 128 * t;
            const int kr = i >> 4;
            const int c  = (i & 15) << 2;
            float4 vb = *(const float4*)(Wm + (size_t)(k0 + kr) * 256 + n0 + c);
            Ws[kr][c + 0] = __uint_as_float(f2tf32(vb.x));
            Ws[kr][c + 1] = __uint_as_float(f2tf32(vb.y));
            Ws[kr][c + 2] = __uint_as_float(f2tf32(vb.z));
            Ws[kr][c + 3] = __uint_as_float(f2tf32(vb.w));
        }
        __syncthreads();

#pragma unroll
        for (int kc = 0; kc < 2; kc++) {
            uint32_t af[2][4];
#pragma unroll
            for (int t = 0; t < 2; t++) {
                const int rb = w * 32 + t * 16;
                af[t][0] = __float_as_uint(As[rb + g    ][kc * 8 + tig    ]);
                af[t][1] = __float_as_uint(As[rb + g + 8][kc * 8 + tig    ]);
                af[t][2] = __float_as_uint(As[rb + g    ][kc * 8 + tig + 4]);
                af[t][3] = __float_as_uint(As[rb + g + 8][kc * 8 + tig + 4]);
            }
#pragma unroll
            for (int nt = 0; nt < 8; nt++) {
                const uint32_t b0 = __float_as_uint(Ws[kc * 8 + tig    ][nt * 8 + g]);
                const uint32_t b1 = __float_as_uint(Ws[kc * 8 + tig + 4][nt * 8 + g]);
#pragma unroll
                for (int t = 0; t < 2; t++)
                    mma_tf32(acc[t][nt][0], acc[t][nt][1], acc[t][nt][2], acc[t][nt][3],
                             af[t][0], af[t][1], af[t][2], af[t][3], b0, b1);
            }
        }
        __syncthreads();
    }

    // ---- epilogue ----
#pragma unroll
    for (int t = 0; t < 2; t++) {
#pragma unroll
        for (int nt = 0; nt < 8; nt++) {
#pragma unroll
            for (int half = 0; half < 2; half++) {
                const int r = m0 + w * 32 + t * 16 + g + half * 8;
#pragma unroll
                for (int j = 0; j < 2; j++) {
                    const int c   = n0 + nt * 8 + 2 * tig + j;
                    float val     = acc[t][nt][half * 2 + j] + __ldg(bias + c);
                    const int n   = c >> 5;
                    const int d   = c & 31;
                    if (MODE == 0) {
                        val *= 0.17677669529663687f;
                        const int b = r >> 10, p = r & 1023;
                        g_q[(((b * NH + n) * P2) + p) * DK + d] =
                            __uint_as_float(f2tf32(val));
                    } else if (MODE == 1) {
                        const int b = r >> 12, ii = r & 4095;
                        g_k[(((b * NH + n) * HW) + ii) * DK + d] =
                            __uint_as_float(f2tf32(val));
                    } else {
                        val = val / (1.0f + __expf(-val));
                        const int b = r >> 12, ii = r & 4095;
                        g_v[(((size_t)(b * NH + n) * DV) + d) * HW + ii] = __float2half_rn(val);
                    }
                }
            }
        }
    }
}

// ---------------------------------------------------------------------------
// Flash attention: tf32 QK^T + fp16 PV (register-resident P), cp.async
// double-buffered K/V staging. Block: 4 warps, 64 queries (warp: 16 rows).
// ---------------------------------------------------------------------------
__global__ __launch_bounds__(128)
void attn_tc_kernel(float* __restrict__ out)
{
    __shared__ float  Qs[64][36];          // staged once
    __shared__ float  Ks[2][64][36];       // double-buffered, tf32-ready
    __shared__ __half VsT[2][32][72];      // [dim][key], double-buffered

    const int tid  = threadIdx.x;
    const int w    = tid >> 5;
    const int lane = tid & 31;
    const int g    = lane >> 2;
    const int tig  = lane & 3;

    const int qt = blockIdx.x;
    const int n  = blockIdx.y;
    const int b  = blockIdx.z;
    const int bn = b * NH + n;

    const float*  qglob = g_q + (size_t)(bn * P2 + qt * 64) * DK;
    const float*  kglob = g_k + (size_t)bn * HW * DK;
    const __half* vglob = g_v + (size_t)bn * DV * HW;

    const uint32_t ks_base  = (uint32_t)__cvta_generic_to_shared(&Ks[0][0][0]);
    const uint32_t vst_base = (uint32_t)__cvta_generic_to_shared(&VsT[0][0][0]);

    // ---- stage Q once (already tf32-rounded) ----
#pragma unroll
    for (int t = 0; t < 4; t++) {
        const int i   = tid + 128 * t;     // 512 float4
        const int row = i >> 3;
        const int c   = (i & 7) << 2;
        *(float4*)&Qs[row][c] = *(const float4*)(qglob + row * 32 + c);
    }

    // ---- async stage of tile j0 into buffer buf ----
    auto stage = [&](int j0, int buf) {
        // K: 64 rows x 128B = 512 chunks of 16B
#pragma unroll
        for (int t = 0; t < 4; t++) {
            const int i   = tid + 128 * t;
            const int row = i >> 3;
            const int c   = i & 7;
            cpa16(ks_base + (uint32_t)(buf * 64 * 36 + row * 36 + c * 4) * 4,
                  kglob + (size_t)(j0 + row) * 32 + c * 4);
        }
        // V^T: 32 rows x 128B = 256 chunks of 16B
#pragma unroll
        for (int t = 0; t < 2; t++) {
            const int i   = tid + 128 * t;
            const int row = i >> 3;
            const int c   = i & 7;
            cpa16(vst_base + (uint32_t)(buf * 32 * 72 + row * 72 + c * 8) * 2,
                  vglob + (size_t)row * HW + j0 + c * 8);
        }
    };

    stage(0, 0);
    cpa_commit();
    __syncthreads();   // Qs visible

    // ---- Q fragments in registers ----
    uint32_t Qf[4][4];
    const int r0 = w * 16 + g;
#pragma unroll
    for (int kc = 0; kc < 4; kc++) {
        Qf[kc][0] = __float_as_uint(Qs[r0    ][kc * 8 + tig    ]);
        Qf[kc][1] = __float_as_uint(Qs[r0 + 8][kc * 8 + tig    ]);
        Qf[kc][2] = __float_as_uint(Qs[r0    ][kc * 8 + tig + 4]);
        Qf[kc][3] = __float_as_uint(Qs[r0 + 8][kc * 8 + tig + 4]);
    }

    float m0 = -INFINITY, m1 = -INFINITY, l0 = 0.0f, l1 = 0.0f;
    float oacc[4][4];
#pragma unroll
    for (int i = 0; i < 4; i++)
#pragma unroll
        for (int j = 0; j < 4; j++) oacc[i][j] = 0.0f;

    for (int it = 0; it < HW / 64; it++) {
        const int buf = it & 1;
        if (it + 1 < HW / 64) stage((it + 1) * 64, buf ^ 1);
        cpa_commit();
        cpa_wait<1>();       // tile `it` complete (next tile may be in flight)
        __syncthreads();

        // ---- S = Q K^T (tf32) ----
        float sacc[8][4];
#pragma unroll
        for (int nt = 0; nt < 8; nt++)
#pragma unroll
            for (int j = 0; j < 4; j++) sacc[nt][j] = 0.0f;

#pragma unroll
        for (int kc = 0; kc < 4; kc++) {
#pragma unroll
            for (int nt = 0; nt < 8; nt++) {
                const uint32_t b0 = __float_as_uint(Ks[buf][nt * 8 + g][kc * 8 + tig    ]);
                const uint32_t b1 = __float_as_uint(Ks[buf][nt * 8 + g][kc * 8 + tig + 4]);
                mma_tf32(sacc[nt][0], sacc[nt][1], sacc[nt][2], sacc[nt][3],
                         Qf[kc][0], Qf[kc][1], Qf[kc][2], Qf[kc][3], b0, b1);
            }
        }

        // ---- online softmax ----
        float mx0 = -INFINITY, mx1 = -INFINITY;
#pragma unroll
        for (int nt = 0; nt < 8; nt++) {
            mx0 = fmaxf(mx0, fmaxf(sacc[nt][0], sacc[nt][1]));
            mx1 = fmaxf(mx1, fmaxf(sacc[nt][2], sacc[nt][3]));
        }
        mx0 = fmaxf(mx0, __shfl_xor_sync(0xffffffffu, mx0, 1));
        mx0 = fmaxf(mx0, __shfl_xor_sync(0xffffffffu, mx0, 2));
        mx1 = fmaxf(mx1, __shfl_xor_sync(0xffffffffu, mx1, 1));
        mx1 = fmaxf(mx1, __shfl_xor_sync(0xffffffffu, mx1, 2));

        const float nm0 = fmaxf(m0, mx0);
        const float nm1 = fmaxf(m1, mx1);
        const float sc0 = __expf(m0 - nm0);
        const float sc1 = __expf(m1 - nm1);
        m0 = nm0; m1 = nm1;

        // exp -> f16x2 fragments (register-resident P, FA2 layout identity)
        uint32_t hlo[8], hhi[8];
        float rs0 = 0.0f, rs1 = 0.0f;
#pragma unroll
        for (int nt = 0; nt < 8; nt++) {
            const float p0 = __expf(sacc[nt][0] - nm0);
            const float p1 = __expf(sacc[nt][1] - nm0);
            const float p2 = __expf(sacc[nt][2] - nm1);
            const float p3 = __expf(sacc[nt][3] - nm1);
            rs0 += p0 + p1;
            rs1 += p2 + p3;
            hlo[nt] = __half2_raw(__floats2half2_rn(p0, p1)).x |
                      ((uint32_t)__half2_raw(__floats2half2_rn(p0, p1)).y << 16);
            // NOTE: construct packed f16x2 directly:
            __half2 h0 = __floats2half2_rn(p0, p1);
            __half2 h1 = __floats2half2_rn(p2, p3);
            hlo[nt] = *(uint32_t*)&h0;
            hhi[nt] = *(uint32_t*)&h1;
        }
        rs0 += __shfl_xor_sync(0xffffffffu, rs0, 1);
        rs0 += __shfl_xor_sync(0xffffffffu, rs0, 2);
        rs1 += __shfl_xor_sync(0xffffffffu, rs1, 1);
        rs1 += __shfl_xor_sync(0xffffffffu, rs1, 2);
        l0 = l0 * sc0 + rs0;
        l1 = l1 * sc1 + rs1;

#pragma unroll
        for (int nt = 0; nt < 4; nt++) {
            oacc[nt][0] *= sc0; oacc[nt][1] *= sc0;
            oacc[nt][2] *= sc1; oacc[nt][3] *= sc1;
        }

        // ---- O += P V (fp16 m16n8k16, k = 16 keys per step) ----
#pragma unroll
        for (int kc = 0; kc < 4; kc++) {
            const uint32_t a0 = hlo[2 * kc];
            const uint32_t a1 = hhi[2 * kc];
            const uint32_t a2 = hlo[2 * kc + 1];
            const uint32_t a3 = hhi[2 * kc + 1];
#pragma unroll
            for (int nt = 0; nt < 4; nt++) {
                const int d = nt * 8 + g;
                const uint32_t b0 = *(const uint32_t*)&VsT[buf][d][kc * 16 + 2 * tig    ];
                const uint32_t b1 = *(const uint32_t*)&VsT[buf][d][kc * 16 + 2 * tig + 8];
                mma_f16(oacc[nt][0], oacc[nt][1], oacc[nt][2], oacc[nt][3],
                        a0, a1, a2, a3, b0, b1);
            }
        }
        __syncthreads();   // all warps done with buf before it is re-staged
    }

    // ---- epilogue ----
    const float i0 = 1.0f / l0;
    const float i1 = 1.0f / l1;
    const int q0 = qt * 64 + w * 16 + g;
    float* op0 = out + ((size_t)(b * P2 + q0    ) * 256) + n * DV;
    float* op1 = out + ((size_t)(b * P2 + q0 + 8) * 256) + n * DV;
#pragma unroll
    for (int nt = 0; nt < 4; nt++) {
        *(float2*)(op0 + nt * 8 + 2 * tig) = make_float2(oacc[nt][0] * i0, oacc[nt][1] * i0);
        *(float2*)(op1 + nt * 8 + 2 * tig) = make_float2(oacc[nt][2] * i1, oacc[nt][3] * i1);
    }
}

// ---------------------------------------------------------------------------
extern "C" void kernel_launch(void* const* d_in, const int* in_sizes, int n_in,
                              void* d_out, int out_size)
{
    const float* blob = (const float*)d_in[0];
    const float* wq   = (const float*)d_in[1];
    const float* bq   = (const float*)d_in[2];
    const float* wk   = (const float*)d_in[3];
    const float* bk   = (const float*)d_in[4];
    const float* wv   = (const float*)d_in[5];
    const float* bv   = (const float*)d_in[6];
    float* out        = (float*)d_out;

    proj_tc_kernel<0><<<dim3(4, 32),  128>>>(blob, wq, bq);   // Q: M=4096
    proj_tc_kernel<1><<<dim3(4, 128), 128>>>(blob, wk, bk);   // K: M=16384
    proj_tc_kernel<2><<<dim3(4, 128), 128>>>(blob, wv, bv);   // V: M=16384

    attn_tc_kernel<<<dim3(16, NH, BB), 128>>>(out);
}

// round 5
// speedup vs baseline: 4.9903x; 1.2265x over previous
#include <cuda_runtime.h>
#include <cuda_fp16.h>
#include <math.h>
#include <stdint.h>

// Problem constants
#define BB 4
#define HH 64
#define WW 64
#define DD 256
#define NH 8
#define DK 32
#define DV 32
#define HW 4096
#define P2 1024
#define SPLIT 2
#define KSPS 2048        // keys per split

// Scratch
__device__ __half g_q[BB * NH * P2 * DK];        // 2 MB [bn][p][k]  (pre-scaled by 1/sqrt(K)*log2e)
__device__ __half g_k[BB * NH * HW * DK];        // 8 MB [bn][i][k]
__device__ __half g_v[BB * NH * DV * HW];        // 8 MB [bn][d][i]  TRANSPOSED
__device__ float  g_po[SPLIT][BB * NH * P2 * DV];// 8 MB unnormalized partial O
__device__ float  g_pm[SPLIT][BB * NH * P2];     // partial max (log2 domain)
__device__ float  g_pl[SPLIT][BB * NH * P2];     // partial sum

// ---------------------------------------------------------------------------
__device__ __forceinline__ uint32_t f2tf32(float f) {
    uint32_t u;
    asm("cvt.rna.tf32.f32 %0, %1;" : "=r"(u) : "f"(f));
    return u;
}
__device__ __forceinline__ float ex2f(float x) {
    float r;
    asm("ex2.approx.ftz.f32 %0, %1;" : "=f"(r) : "f"(x));
    return r;
}
__device__ __forceinline__ void mma_tf32(float& d0, float& d1, float& d2, float& d3,
                                         uint32_t a0, uint32_t a1, uint32_t a2, uint32_t a3,
                                         uint32_t b0, uint32_t b1) {
    asm volatile(
        "mma.sync.aligned.m16n8k8.row.col.f32.tf32.tf32.f32 "
        "{%0,%1,%2,%3}, {%4,%5,%6,%7}, {%8,%9}, {%0,%1,%2,%3};\n"
        : "+f"(d0), "+f"(d1), "+f"(d2), "+f"(d3)
        : "r"(a0), "r"(a1), "r"(a2), "r"(a3), "r"(b0), "r"(b1));
}
__device__ __forceinline__ void mma_f16(float& d0, float& d1, float& d2, float& d3,
                                        uint32_t a0, uint32_t a1, uint32_t a2, uint32_t a3,
                                        uint32_t b0, uint32_t b1) {
    asm volatile(
        "mma.sync.aligned.m16n8k16.row.col.f32.f16.f16.f32 "
        "{%0,%1,%2,%3}, {%4,%5,%6,%7}, {%8,%9}, {%0,%1,%2,%3};\n"
        : "+f"(d0), "+f"(d1), "+f"(d2), "+f"(d3)
        : "r"(a0), "r"(a1), "r"(a2), "r"(a3), "r"(b0), "r"(b1));
}
__device__ __forceinline__ void cpa16(uint32_t s, const void* g) {
    asm volatile("cp.async.ca.shared.global [%0], [%1], 16;\n" :: "r"(s), "l"(g));
}
__device__ __forceinline__ void cpa_commit() { asm volatile("cp.async.commit_group;\n"); }
template <int N>
__device__ __forceinline__ void cpa_wait() { asm volatile("cp.async.wait_group %0;\n" :: "n"(N)); }

// ---------------------------------------------------------------------------
// Merged tf32 projections: one launch, 1152 blocks.
//   blk [0,128):    Q  (fused maxpool; scale 1/sqrt(K)*log2e; -> g_q f16)
//   blk [128,640):  K  (-> g_k f16)
//   blk [640,1152): V  (swish; -> g_v f16 transposed)
// Block: 128 thr / 4 warps. Tile M=128, N=64, k-step 16.
// ---------------------------------------------------------------------------
__global__ __launch_bounds__(128)
void proj_all_kernel(const float* __restrict__ A,
                     const float* __restrict__ wq, const float* __restrict__ bq,
                     const float* __restrict__ wk, const float* __restrict__ bk,
                     const float* __restrict__ wv, const float* __restrict__ bv)
{
    __shared__ float As[128][20];
    __shared__ float Ws[16][68];

    const int tid  = threadIdx.x;
    const int w    = tid >> 5;
    const int lane = tid & 31;
    const int g    = lane >> 2;
    const int tig  = lane & 3;

    const int blk = blockIdx.x;
    int mode, mt;
    if (blk < 128)      { mode = 0; mt = blk >> 2; }
    else if (blk < 640) { mode = 1; mt = (blk - 128) >> 2; }
    else                { mode = 2; mt = (blk - 640) >> 2; }
    const int n0 = (blk & 3) << 6;
    const int m0 = mt << 7;

    const float* Wm   = (mode == 0) ? wq : (mode == 1) ? wk : wv;
    const float* bias = (mode == 0) ? bq : (mode == 1) ? bk : bv;

    float acc[2][8][4];
#pragma unroll
    for (int t = 0; t < 2; t++)
#pragma unroll
        for (int nt = 0; nt < 8; nt++)
#pragma unroll
            for (int j = 0; j < 4; j++) acc[t][nt][j] = 0.0f;

    for (int k0 = 0; k0 < DD; k0 += 16) {
#pragma unroll
        for (int t = 0; t < 4; t++) {
            const int i   = tid + 128 * t;
            const int row = i >> 2;
            const int c4  = (i & 3) << 2;
            const int r   = m0 + row;
            float4 va;
            if (mode == 0) {
                const int b  = r >> 10;
                const int l  = r & 1023;
                const int h2 = l >> 5;
                const int w2 = l & 31;
                const float* p00 = A + ((b * HH + 2 * h2) * WW + 2 * w2) * DD + k0 + c4;
                float4 v0 = *(const float4*)(p00);
                float4 v1 = *(const float4*)(p00 + DD);
                float4 v2 = *(const float4*)(p00 + WW * DD);
                float4 v3 = *(const float4*)(p00 + WW * DD + DD);
                va.x = fmaxf(fmaxf(v0.x, v1.x), fmaxf(v2.x, v3.x));
                va.y = fmaxf(fmaxf(v0.y, v1.y), fmaxf(v2.y, v3.y));
                va.z = fmaxf(fmaxf(v0.z, v1.z), fmaxf(v2.z, v3.z));
                va.w = fmaxf(fmaxf(v0.w, v1.w), fmaxf(v2.w, v3.w));
            } else {
                va = *(const float4*)(A + (size_t)r * DD + k0 + c4);
            }
            As[row][c4 + 0] = __uint_as_float(f2tf32(va.x));
            As[row][c4 + 1] = __uint_as_float(f2tf32(va.y));
            As[row][c4 + 2] = __uint_as_float(f2tf32(va.z));
            As[row][c4 + 3] = __uint_as_float(f2tf32(va.w));
        }
#pragma unroll
        for (int t = 0; t < 2; t++) {
            const int i  = tid + 128 * t;
            const int kr = i >> 4;
            const int c  = (i & 15) << 2;
            float4 vb = *(const float4*)(Wm + (size_t)(k0 + kr) * 256 + n0 + c);
            Ws[kr][c + 0] = __uint_as_float(f2tf32(vb.x));
            Ws[kr][c + 1] = __uint_as_float(f2tf32(vb.y));
            Ws[kr][c + 2] = __uint_as_float(f2tf32(vb.z));
            Ws[kr][c + 3] = __uint_as_float(f2tf32(vb.w));
        }
        __syncthreads();

#pragma unroll
        for (int kc = 0; kc < 2; kc++) {
            uint32_t af[2][4];
#pragma unroll
            for (int t = 0; t < 2; t++) {
                const int rb = w * 32 + t * 16;
                af[t][0] = __float_as_uint(As[rb + g    ][kc * 8 + tig    ]);
                af[t][1] = __float_as_uint(As[rb + g + 8][kc * 8 + tig    ]);
                af[t][2] = __float_as_uint(As[rb + g    ][kc * 8 + tig + 4]);
                af[t][3] = __float_as_uint(As[rb + g + 8][kc * 8 + tig + 4]);
            }
#pragma unroll
            for (int nt = 0; nt < 8; nt++) {
                const uint32_t b0 = __float_as_uint(Ws[kc * 8 + tig    ][nt * 8 + g]);
                const uint32_t b1 = __float_as_uint(Ws[kc * 8 + tig + 4][nt * 8 + g]);
#pragma unroll
                for (int t = 0; t < 2; t++)
                    mma_tf32(acc[t][nt][0], acc[t][nt][1], acc[t][nt][2], acc[t][nt][3],
                             af[t][0], af[t][1], af[t][2], af[t][3], b0, b1);
            }
        }
        __syncthreads();
    }

    // ---- epilogue -> f16 scratch ----
    const float QSCL = 0.17677669529663687f * 1.4426950408889634f; // 1/sqrt(32)*log2e
#pragma unroll
    for (int t = 0; t < 2; t++) {
#pragma unroll
        for (int nt = 0; nt < 8; nt++) {
#pragma unroll
            for (int half = 0; half < 2; half++) {
                const int r = m0 + w * 32 + t * 16 + g + half * 8;
#pragma unroll
                for (int j = 0; j < 2; j++) {
                    const int c = n0 + nt * 8 + 2 * tig + j;
                    float val   = acc[t][nt][half * 2 + j] + __ldg(bias + c);
                    const int n = c >> 5;
                    const int d = c & 31;
                    if (mode == 0) {
                        val *= QSCL;
                        const int b = r >> 10, p = r & 1023;
                        g_q[(((b * NH + n) * P2) + p) * DK + d] = __float2half_rn(val);
                    } else if (mode == 1) {
                        const int b = r >> 12, ii = r & 4095;
                        g_k[(((b * NH + n) * HW) + ii) * DK + d] = __float2half_rn(val);
                    } else {
                        val = val / (1.0f + __expf(-val));
                        const int b = r >> 12, ii = r & 4095;
                        g_v[(((size_t)(b * NH + n) * DV) + d) * HW + ii] = __float2half_rn(val);
                    }
                }
            }
        }
    }
}

// ---------------------------------------------------------------------------
// Split-K fp16 flash attention. Block: 4 warps / 64 queries; 2048 keys/block.
// QK^T and PV both fp16 m16n8k16, f32 accum. exp2-domain softmax.
// Writes unnormalized partials; combine kernel merges the two splits.
// ---------------------------------------------------------------------------
__global__ __launch_bounds__(128)
void attn_tc_kernel()
{
    __shared__ __half Qs[64][40];
    __shared__ __half Ks[2][64][40];
    __shared__ __half VsT[2][32][72];

    const int tid  = threadIdx.x;
    const int w    = tid >> 5;
    const int lane = tid & 31;
    const int g    = lane >> 2;
    const int tig  = lane & 3;

    const int qt = blockIdx.x;            // 0..15
    const int n  = blockIdx.y;            // head
    const int z  = blockIdx.z;            // 0..7
    const int b  = z >> 1;
    const int s  = z & 1;                 // key split
    const int bn = b * NH + n;

    const __half* qglob = g_q + (size_t)(bn * P2 + qt * 64) * DK;
    const __half* kglob = g_k + ((size_t)bn * HW + s * KSPS) * DK;
    const __half* vglob = g_v + (size_t)bn * DV * HW + s * KSPS;

    const uint32_t ks_base  = (uint32_t)__cvta_generic_to_shared(&Ks[0][0][0]);
    const uint32_t vst_base = (uint32_t)__cvta_generic_to_shared(&VsT[0][0][0]);

    // stage Q once: 64 rows x 64B = 256 x 16B
#pragma unroll
    for (int t = 0; t < 2; t++) {
        const int i   = tid + 128 * t;
        const int row = i >> 2;
        const int c   = i & 3;
        *(float4*)&Qs[row][c * 8] = *(const float4*)(qglob + row * DK + c * 8);
    }

    auto stage = [&](int j0, int buf) {
        // K: 64 rows x 64B
#pragma unroll
        for (int t = 0; t < 2; t++) {
            const int i   = tid + 128 * t;
            const int row = i >> 2;
            const int c   = i & 3;
            cpa16(ks_base + (uint32_t)(buf * 64 * 40 + row * 40 + c * 8) * 2,
                  kglob + (size_t)(j0 + row) * DK + c * 8);
        }
        // V^T: 32 rows x 128B
#pragma unroll
        for (int t = 0; t < 2; t++) {
            const int i   = tid + 128 * t;
            const int row = i >> 3;
            const int c   = i & 7;
            cpa16(vst_base + (uint32_t)(buf * 32 * 72 + row * 72 + c * 8) * 2,
                  vglob + (size_t)row * HW + j0 + c * 8);
        }
    };

    stage(0, 0);
    cpa_commit();
    __syncthreads();

    // Q fragments (m16n8k16 A): 2 k-chunks x 4 regs
    uint32_t Qf[2][4];
    const int r0 = w * 16 + g;
#pragma unroll
    for (int kc = 0; kc < 2; kc++) {
        Qf[kc][0] = *(const uint32_t*)&Qs[r0    ][kc * 16 + 2 * tig    ];
        Qf[kc][1] = *(const uint32_t*)&Qs[r0 + 8][kc * 16 + 2 * tig    ];
        Qf[kc][2] = *(const uint32_t*)&Qs[r0    ][kc * 16 + 2 * tig + 8];
        Qf[kc][3] = *(const uint32_t*)&Qs[r0 + 8][kc * 16 + 2 * tig + 8];
    }

    float m0 = -INFINITY, m1 = -INFINITY, l0 = 0.0f, l1 = 0.0f;
    float oacc[4][4];
#pragma unroll
    for (int i = 0; i < 4; i++)
#pragma unroll
        for (int j = 0; j < 4; j++) oacc[i][j] = 0.0f;

    for (int it = 0; it < KSPS / 64; it++) {
        const int buf = it & 1;
        if (it + 1 < KSPS / 64) stage((it + 1) * 64, buf ^ 1);
        cpa_commit();
        cpa_wait<1>();
        __syncthreads();

        // ---- S = Q K^T (fp16, log2-domain scores) ----
        float sacc[8][4];
#pragma unroll
        for (int nt = 0; nt < 8; nt++)
#pragma unroll
            for (int j = 0; j < 4; j++) sacc[nt][j] = 0.0f;

#pragma unroll
        for (int kc = 0; kc < 2; kc++) {
#pragma unroll
            for (int nt = 0; nt < 8; nt++) {
                const uint32_t b0 = *(const uint32_t*)&Ks[buf][nt * 8 + g][kc * 16 + 2 * tig    ];
                const uint32_t b1 = *(const uint32_t*)&Ks[buf][nt * 8 + g][kc * 16 + 2 * tig + 8];
                mma_f16(sacc[nt][0], sacc[nt][1], sacc[nt][2], sacc[nt][3],
                        Qf[kc][0], Qf[kc][1], Qf[kc][2], Qf[kc][3], b0, b1);
            }
        }

        // ---- online softmax (exp2) ----
        float mx0 = -INFINITY, mx1 = -INFINITY;
#pragma unroll
        for (int nt = 0; nt < 8; nt++) {
            mx0 = fmaxf(mx0, fmaxf(sacc[nt][0], sacc[nt][1]));
            mx1 = fmaxf(mx1, fmaxf(sacc[nt][2], sacc[nt][3]));
        }
        mx0 = fmaxf(mx0, __shfl_xor_sync(0xffffffffu, mx0, 1));
        mx0 = fmaxf(mx0, __shfl_xor_sync(0xffffffffu, mx0, 2));
        mx1 = fmaxf(mx1, __shfl_xor_sync(0xffffffffu, mx1, 1));
        mx1 = fmaxf(mx1, __shfl_xor_sync(0xffffffffu, mx1, 2));

        const float nm0 = fmaxf(m0, mx0);
        const float nm1 = fmaxf(m1, mx1);
        const float sc0 = ex2f(m0 - nm0);   // ex2(-inf)=0 first tile
        const float sc1 = ex2f(m1 - nm1);
        m0 = nm0; m1 = nm1;

        uint32_t hlo[8], hhi[8];
        float rs0 = 0.0f, rs1 = 0.0f;
#pragma unroll
        for (int nt = 0; nt < 8; nt++) {
            const float p0 = ex2f(sacc[nt][0] - nm0);
            const float p1 = ex2f(sacc[nt][1] - nm0);
            const float p2 = ex2f(sacc[nt][2] - nm1);
            const float p3 = ex2f(sacc[nt][3] - nm1);
            rs0 += p0 + p1;
            rs1 += p2 + p3;
            __half2 h0 = __floats2half2_rn(p0, p1);
            __half2 h1 = __floats2half2_rn(p2, p3);
            hlo[nt] = *(uint32_t*)&h0;
            hhi[nt] = *(uint32_t*)&h1;
        }
        rs0 += __shfl_xor_sync(0xffffffffu, rs0, 1);
        rs0 += __shfl_xor_sync(0xffffffffu, rs0, 2);
        rs1 += __shfl_xor_sync(0xffffffffu, rs1, 1);
        rs1 += __shfl_xor_sync(0xffffffffu, rs1, 2);
        l0 = l0 * sc0 + rs0;
        l1 = l1 * sc1 + rs1;

#pragma unroll
        for (int nt = 0; nt < 4; nt++) {
            oacc[nt][0] *= sc0; oacc[nt][1] *= sc0;
            oacc[nt][2] *= sc1; oacc[nt][3] *= sc1;
        }

        // ---- O += P V (fp16, register-resident P) ----
#pragma unroll
        for (int kc = 0; kc < 4; kc++) {
            const uint32_t a0 = hlo[2 * kc];
            const uint32_t a1 = hhi[2 * kc];
            const uint32_t a2 = hlo[2 * kc + 1];
            const uint32_t a3 = hhi[2 * kc + 1];
#pragma unroll
            for (int nt = 0; nt < 4; nt++) {
                const int d = nt * 8 + g;
                const uint32_t b0 = *(const uint32_t*)&VsT[buf][d][kc * 16 + 2 * tig    ];
                const uint32_t b1 = *(const uint32_t*)&VsT[buf][d][kc * 16 + 2 * tig + 8];
                mma_f16(oacc[nt][0], oacc[nt][1], oacc[nt][2], oacc[nt][3],
                        a0, a1, a2, a3, b0, b1);
            }
        }
        __syncthreads();
    }

    // ---- write partials (unnormalized) ----
    const int q0   = qt * 64 + w * 16 + g;
    const int row0 = bn * P2 + q0;
    const int row1 = row0 + 8;
    if (tig == 0) {
        g_pm[s][row0] = m0;  g_pl[s][row0] = l0;
        g_pm[s][row1] = m1;  g_pl[s][row1] = l1;
    }
    float* po0 = &g_po[s][(size_t)row0 * DV];
    float* po1 = &g_po[s][(size_t)row1 * DV];
#pragma unroll
    for (int nt = 0; nt < 4; nt++) {
        *(float2*)(po0 + nt * 8 + 2 * tig) = make_float2(oacc[nt][0], oacc[nt][1]);
        *(float2*)(po1 + nt * 8 + 2 * tig) = make_float2(oacc[nt][2], oacc[nt][3]);
    }
}

// ---------------------------------------------------------------------------
// Combine the two key-splits and normalize.
// ---------------------------------------------------------------------------
__global__ __launch_bounds__(256)
void combine_kernel(float* __restrict__ out)
{
    const int idx = blockIdx.x * 256 + threadIdx.x;   // over BB*NH*P2*DV
    const int row = idx >> 5;
    const int d   = idx & 31;

    const float pm0 = g_pm[0][row], pm1 = g_pm[1][row];
    const float M   = fmaxf(pm0, pm1);
    const float w0  = ex2f(pm0 - M);
    const float w1  = ex2f(pm1 - M);
    const float den = g_pl[0][row] * w0 + g_pl[1][row] * w1;
    const float v   = (g_po[0][idx] * w0 + g_po[1][idx] * w1) / den;

    const int b = row >> 13;
    const int n = (row >> 10) & 7;
    const int p = row & 1023;
    out[((size_t)(b * P2 + p) * 256) + n * DV + d] = v;
}

// ---------------------------------------------------------------------------
extern "C" void kernel_launch(void* const* d_in, const int* in_sizes, int n_in,
                              void* d_out, int out_size)
{
    const float* blob = (const float*)d_in[0];
    const float* wq   = (const float*)d_in[1];
    const float* bq   = (const float*)d_in[2];
    const float* wk   = (const float*)d_in[3];
    const float* bk   = (const float*)d_in[4];
    const float* wv   = (const float*)d_in[5];
    const float* bv   = (const float*)d_in[6];
    float* out        = (float*)d_out;

    proj_all_kernel<<<1152, 128>>>(blob, wq, bq, wk, bk, wv, bv);
    attn_tc_kernel<<<dim3(16, NH, BB * SPLIT), 128>>>();
    combine_kernel<<<(BB * NH * P2 * DV) / 256, 256>>>(out);
}

// round 6
// speedup vs baseline: 7.3013x; 1.4631x over previous
#include <cuda_runtime.h>
#include <cuda_fp16.h>
#include <math.h>
#include <stdint.h>

// Problem constants
#define BB 4
#define HH 64
#define WW 64
#define DD 256
#define NH 8
#define DK 32
#define DV 32
#define HW 4096
#define P2 1024
#define SPLIT 2
#define KSPS 2048        // keys per split

// Scratch
__device__ __half g_a16[BB * HW * DD];           //  8 MB blob in f16
__device__ __half g_p16[BB * P2 * DD];           //  2 MB pooled blob f16
__device__ __half g_w16[3 * DD * DD];            // 384 KB weights f16 [mode][n][k]
__device__ __half g_q[BB * NH * P2 * DK];        //  2 MB [bn][p][k] (pre-scaled 1/sqrt(K)*log2e)
__device__ __half g_k[BB * NH * HW * DK];        //  8 MB [bn][i][k]
__device__ __half g_v[BB * NH * DV * HW];        //  8 MB [bn][d][i] TRANSPOSED
__device__ float  g_po[SPLIT][BB * NH * P2 * DV];//  8 MB unnormalized partial O
__device__ float  g_pm[SPLIT][BB * NH * P2];     // partial max (log2 domain)
__device__ float  g_pl[SPLIT][BB * NH * P2];     // partial sum

// ---------------------------------------------------------------------------
__device__ __forceinline__ float ex2f(float x) {
    float r;
    asm("ex2.approx.ftz.f32 %0, %1;" : "=f"(r) : "f"(x));
    return r;
}
__device__ __forceinline__ void mma_f16(float& d0, float& d1, float& d2, float& d3,
                                        uint32_t a0, uint32_t a1, uint32_t a2, uint32_t a3,
                                        uint32_t b0, uint32_t b1) {
    asm volatile(
        "mma.sync.aligned.m16n8k16.row.col.f32.f16.f16.f32 "
        "{%0,%1,%2,%3}, {%4,%5,%6,%7}, {%8,%9}, {%0,%1,%2,%3};\n"
        : "+f"(d0), "+f"(d1), "+f"(d2), "+f"(d3)
        : "r"(a0), "r"(a1), "r"(a2), "r"(a3), "r"(b0), "r"(b1));
}
__device__ __forceinline__ void ldsm_x4(uint32_t& r0, uint32_t& r1, uint32_t& r2, uint32_t& r3,
                                        uint32_t a) {
    asm volatile("ldmatrix.sync.aligned.m8n8.x4.shared.b16 {%0,%1,%2,%3}, [%4];\n"
                 : "=r"(r0), "=r"(r1), "=r"(r2), "=r"(r3) : "r"(a));
}
__device__ __forceinline__ uint32_t smem_u32(const void* p) {
    return (uint32_t)__cvta_generic_to_shared(p);
}
__device__ __forceinline__ void cpa16(uint32_t s, const void* g) {
    asm volatile("cp.async.ca.shared.global [%0], [%1], 16;\n" :: "r"(s), "l"(g));
}
__device__ __forceinline__ void cpa_commit() { asm volatile("cp.async.commit_group;\n"); }
template <int N>
__device__ __forceinline__ void cpa_wait() { asm volatile("cp.async.wait_group %0;\n" :: "n"(N)); }

// ---------------------------------------------------------------------------
// Prep 1: blob f32 -> f16, and fused 2x2 maxpool -> pooled f16.
// One thread: 8 d-channels of one pooled pixel (4 source pixels).
// ---------------------------------------------------------------------------
__global__ __launch_bounds__(256)
void prep_blob(const float* __restrict__ blob)
{
    const int idx = blockIdx.x * 256 + threadIdx.x;    // 131072 total
    const int pp  = idx >> 5;
    const int c8  = (idx & 31) << 3;
    const int b  = pp >> 10, l = pp & 1023, h2 = l >> 5, w2 = l & 31;
    const int pix = (b * HH + 2 * h2) * WW + 2 * w2;
    const float* p = blob + (size_t)pix * DD + c8;

    float mx[8];
#pragma unroll
    for (int j = 0; j < 8; j++) mx[j] = -INFINITY;
    const int offs[4] = {0, DD, WW * DD, WW * DD + DD};
#pragma unroll
    for (int q = 0; q < 4; q++) {
        float4 v0 = *(const float4*)(p + offs[q]);
        float4 v1 = *(const float4*)(p + offs[q] + 4);
        float vv[8] = {v0.x, v0.y, v0.z, v0.w, v1.x, v1.y, v1.z, v1.w};
        __half hh[8];
#pragma unroll
        for (int j = 0; j < 8; j++) {
            hh[j] = __float2half_rn(vv[j]);
            mx[j] = fmaxf(mx[j], vv[j]);
        }
        const int pixq = pix + ((q >> 1) ? WW : 0) + (q & 1);
        *(uint4*)(g_a16 + (size_t)pixq * DD + c8) = *(uint4*)hh;
    }
    __half hm[8];
#pragma unroll
    for (int j = 0; j < 8; j++) hm[j] = __float2half_rn(mx[j]);
    *(uint4*)(g_p16 + (size_t)pp * DD + c8) = *(uint4*)hm;
}

// ---------------------------------------------------------------------------
// Prep 2: weights f32 [k][n] -> f16 transposed [mode][n][k].
// ---------------------------------------------------------------------------
__global__ __launch_bounds__(256)
void prep_w(const float* __restrict__ wq, const float* __restrict__ wk,
            const float* __restrict__ wv)
{
    const int idx = blockIdx.x * 256 + threadIdx.x;    // 24576 total
    const int m   = idx >> 13;                          // 8192 per mode
    const int r   = idx & 8191;
    const int n   = r >> 5;
    const int k0  = (r & 31) << 3;
    const float* Wm = (m == 0) ? wq : (m == 1) ? wk : wv;
    __half tmp[8];
#pragma unroll
    for (int j = 0; j < 8; j++)
        tmp[j] = __float2half_rn(Wm[(size_t)(k0 + j) * DD + n]);
    *(uint4*)(g_w16 + ((size_t)m * DD + n) * DD + k0) = *(uint4*)tmp;
}

// ---------------------------------------------------------------------------
// f16 tensor-core projections, one launch (576 blocks):
//   blk [0,64):    Q  (pooled input; *1/sqrt(K)*log2e; -> g_q)
//   blk [64,320):  K  (-> g_k)
//   blk [320,576): V  (swish; -> g_v transposed)
// Block: 256 thr / 8 warps (4m x 2n). Tile M=128, N=128, k-step 32,
// cp.async double-buffered, ldmatrix fragments.
// ---------------------------------------------------------------------------
__global__ __launch_bounds__(256, 2)
void proj_gemm(const float* __restrict__ bq, const float* __restrict__ bk,
               const float* __restrict__ bv)
{
    __shared__ __half As[2][128][40];
    __shared__ __half Ws[2][128][40];

    const int tid  = threadIdx.x;
    const int w    = tid >> 5;
    const int lane = tid & 31;
    const int g    = lane >> 2;
    const int tig  = lane & 3;
    const int rsel = lane & 7;
    const int quad = lane >> 3;
    const int mw   = w & 3;
    const int nw   = w >> 2;

    const int blk = blockIdx.x;
    int mode, mt, n0;
    if (blk < 64)       { mode = 0; mt = blk >> 1;          n0 = (blk & 1) << 7; }
    else if (blk < 320) { mode = 1; mt = (blk - 64) >> 1;   n0 = (blk & 1) << 7; }
    else                { mode = 2; mt = (blk - 320) >> 1;  n0 = (blk & 1) << 7; }
    const int m0 = mt << 7;

    const __half* Aptr = (mode == 0) ? g_p16 : g_a16;
    const __half* Wptr = g_w16 + (size_t)mode * DD * DD;
    const float*  bias = (mode == 0) ? bq : (mode == 1) ? bk : bv;

    auto stage = [&](int k0, int buf) {
#pragma unroll
        for (int t = 0; t < 2; t++) {
            const int i   = tid + 256 * t;     // 0..511
            const int row = i >> 2;
            const int c   = i & 3;
            cpa16(smem_u32(&As[buf][row][c * 8]), Aptr + (size_t)(m0 + row) * DD + k0 + c * 8);
            cpa16(smem_u32(&Ws[buf][row][c * 8]), Wptr + (size_t)(n0 + row) * DD + k0 + c * 8);
        }
    };

    float acc[2][8][4];
#pragma unroll
    for (int t = 0; t < 2; t++)
#pragma unroll
        for (int nt = 0; nt < 8; nt++)
#pragma unroll
            for (int j = 0; j < 4; j++) acc[t][nt][j] = 0.0f;

    stage(0, 0);
    cpa_commit();

    for (int ks = 0; ks < 8; ks++) {
        const int buf = ks & 1;
        if (ks + 1 < 8) {
            stage((ks + 1) * 32, buf ^ 1);
            cpa_commit();
            cpa_wait<1>();
        } else {
            cpa_wait<0>();
        }
        __syncthreads();

#pragma unroll
        for (int kc = 0; kc < 2; kc++) {
            uint32_t af[2][4];
#pragma unroll
            for (int t = 0; t < 2; t++) {
                const uint32_t addr = smem_u32(
                    &As[buf][mw * 32 + t * 16 + rsel + ((quad & 1) << 3)]
                            [kc * 16 + ((quad >> 1) << 3)]);
                ldsm_x4(af[t][0], af[t][1], af[t][2], af[t][3], addr);
            }
#pragma unroll
            for (int p = 0; p < 4; p++) {
                uint32_t b0, b1, b2, b3;
                const uint32_t addr = smem_u32(
                    &Ws[buf][nw * 64 + p * 16 + rsel + ((quad >> 1) << 3)]
                            [kc * 16 + ((quad & 1) << 3)]);
                ldsm_x4(b0, b1, b2, b3, addr);
#pragma unroll
                for (int t = 0; t < 2; t++) {
                    mma_f16(acc[t][2 * p][0], acc[t][2 * p][1], acc[t][2 * p][2], acc[t][2 * p][3],
                            af[t][0], af[t][1], af[t][2], af[t][3], b0, b1);
                    mma_f16(acc[t][2 * p + 1][0], acc[t][2 * p + 1][1], acc[t][2 * p + 1][2], acc[t][2 * p + 1][3],
                            af[t][0], af[t][1], af[t][2], af[t][3], b2, b3);
                }
            }
        }
        __syncthreads();
    }

    // ---- epilogue -> f16 scratch ----
    const float QSCL = 0.17677669529663687f * 1.4426950408889634f;
#pragma unroll
    for (int t = 0; t < 2; t++) {
#pragma unroll
        for (int nt = 0; nt < 8; nt++) {
#pragma unroll
            for (int half = 0; half < 2; half++) {
                const int r = m0 + mw * 32 + t * 16 + g + half * 8;
#pragma unroll
                for (int j = 0; j < 2; j++) {
                    const int c = n0 + nw * 64 + nt * 8 + 2 * tig + j;
                    float val   = acc[t][nt][half * 2 + j] + __ldg(bias + c);
                    const int n = c >> 5;
                    const int d = c & 31;
                    if (mode == 0) {
                        val *= QSCL;
                        const int b = r >> 10, p2 = r & 1023;
                        g_q[(((b * NH + n) * P2) + p2) * DK + d] = __float2half_rn(val);
                    } else if (mode == 1) {
                        const int b = r >> 12, ii = r & 4095;
                        g_k[(((b * NH + n) * HW) + ii) * DK + d] = __float2half_rn(val);
                    } else {
                        val = val / (1.0f + __expf(-val));
                        const int b = r >> 12, ii = r & 4095;
                        g_v[(((size_t)(b * NH + n) * DV) + d) * HW + ii] = __float2half_rn(val);
                    }
                }
            }
        }
    }
}

// ---------------------------------------------------------------------------
// Split-K fp16 flash attention (ldmatrix fragments).
// Block: 4 warps / 64 queries; 2048 keys/block; exp2-domain softmax.
// ---------------------------------------------------------------------------
__global__ __launch_bounds__(128)
void attn_tc_kernel()
{
    __shared__ __half Qs[64][40];
    __shared__ __half Ks[2][64][40];
    __shared__ __half VsT[2][32][72];

    const int tid  = threadIdx.x;
    const int w    = tid >> 5;
    const int lane = tid & 31;
    const int g    = lane >> 2;
    const int tig  = lane & 3;
    const int rsel = lane & 7;
    const int quad = lane >> 3;

    const int qt = blockIdx.x;
    const int n  = blockIdx.y;
    const int z  = blockIdx.z;
    const int b  = z >> 1;
    const int s  = z & 1;
    const int bn = b * NH + n;

    const __half* qglob = g_q + (size_t)(bn * P2 + qt * 64) * DK;
    const __half* kglob = g_k + ((size_t)bn * HW + s * KSPS) * DK;
    const __half* vglob = g_v + (size_t)bn * DV * HW + s * KSPS;

    // stage Q once
#pragma unroll
    for (int t = 0; t < 2; t++) {
        const int i   = tid + 128 * t;
        const int row = i >> 2;
        const int c   = i & 3;
        *(float4*)&Qs[row][c * 8] = *(const float4*)(qglob + row * DK + c * 8);
    }

    auto stage = [&](int j0, int buf) {
#pragma unroll
        for (int t = 0; t < 2; t++) {
            const int i   = tid + 128 * t;
            const int row = i >> 2;
            const int c   = i & 3;
            cpa16(smem_u32(&Ks[buf][row][c * 8]), kglob + (size_t)(j0 + row) * DK + c * 8);
        }
#pragma unroll
        for (int t = 0; t < 2; t++) {
            const int i   = tid + 128 * t;
            const int row = i >> 3;
            const int c   = i & 7;
            cpa16(smem_u32(&VsT[buf][row][c * 8]), vglob + (size_t)row * HW + j0 + c * 8);
        }
    };

    stage(0, 0);
    cpa_commit();
    __syncthreads();

    uint32_t Qf[2][4];
    const int r0 = w * 16 + g;
#pragma unroll
    for (int kc = 0; kc < 2; kc++) {
        Qf[kc][0] = *(const uint32_t*)&Qs[r0    ][kc * 16 + 2 * tig    ];
        Qf[kc][1] = *(const uint32_t*)&Qs[r0 + 8][kc * 16 + 2 * tig    ];
        Qf[kc][2] = *(const uint32_t*)&Qs[r0    ][kc * 16 + 2 * tig + 8];
        Qf[kc][3] = *(const uint32_t*)&Qs[r0 + 8][kc * 16 + 2 * tig + 8];
    }

    float m0 = -INFINITY, m1 = -INFINITY, l0 = 0.0f, l1 = 0.0f;
    float oacc[4][4];
#pragma unroll
    for (int i = 0; i < 4; i++)
#pragma unroll
        for (int j = 0; j < 4; j++) oacc[i][j] = 0.0f;

    for (int it = 0; it < KSPS / 64; it++) {
        const int buf = it & 1;
        if (it + 1 < KSPS / 64) {
            stage((it + 1) * 64, buf ^ 1);
            cpa_commit();
            cpa_wait<1>();
        } else {
            cpa_wait<0>();
        }
        __syncthreads();

        // ---- S = Q K^T ----
        float sacc[8][4];
#pragma unroll
        for (int nt = 0; nt < 8; nt++)
#pragma unroll
            for (int j = 0; j < 4; j++) sacc[nt][j] = 0.0f;

#pragma unroll
        for (int kc = 0; kc < 2; kc++) {
#pragma unroll
            for (int p = 0; p < 4; p++) {
                uint32_t b0, b1, b2, b3;
                const uint32_t addr = smem_u32(
                    &Ks[buf][p * 16 + rsel + ((quad >> 1) << 3)]
                            [kc * 16 + ((quad & 1) << 3)]);
                ldsm_x4(b0, b1, b2, b3, addr);
                mma_f16(sacc[2 * p][0], sacc[2 * p][1], sacc[2 * p][2], sacc[2 * p][3],
                        Qf[kc][0], Qf[kc][1], Qf[kc][2], Qf[kc][3], b0, b1);
                mma_f16(sacc[2 * p + 1][0], sacc[2 * p + 1][1], sacc[2 * p + 1][2], sacc[2 * p + 1][3],
                        Qf[kc][0], Qf[kc][1], Qf[kc][2], Qf[kc][3], b2, b3);
            }
        }

        // ---- online softmax (exp2) ----
        float mx0 = -INFINITY, mx1 = -INFINITY;
#pragma unroll
        for (int nt = 0; nt < 8; nt++) {
            mx0 = fmaxf(mx0, fmaxf(sacc[nt][0], sacc[nt][1]));
            mx1 = fmaxf(mx1, fmaxf(sacc[nt][2], sacc[nt][3]));
        }
        mx0 = fmaxf(mx0, __shfl_xor_sync(0xffffffffu, mx0, 1));
        mx0 = fmaxf(mx0, __shfl_xor_sync(0xffffffffu, mx0, 2));
        mx1 = fmaxf(mx1, __shfl_xor_sync(0xffffffffu, mx1, 1));
        mx1 = fmaxf(mx1, __shfl_xor_sync(0xffffffffu, mx1, 2));

        const float nm0 = fmaxf(m0, mx0);
        const float nm1 = fmaxf(m1, mx1);
        const float sc0 = ex2f(m0 - nm0);
        const float sc1 = ex2f(m1 - nm1);
        m0 = nm0; m1 = nm1;

        uint32_t hlo[8], hhi[8];
        float rs0 = 0.0f, rs1 = 0.0f;
#pragma unroll
        for (int nt = 0; nt < 8; nt++) {
            const float p0 = ex2f(sacc[nt][0] - nm0);
            const float p1 = ex2f(sacc[nt][1] - nm0);
            const float p2 = ex2f(sacc[nt][2] - nm1);
            const float p3 = ex2f(sacc[nt][3] - nm1);
            rs0 += p0 + p1;
            rs1 += p2 + p3;
            __half2 h0 = __floats2half2_rn(p0, p1);
            __half2 h1 = __floats2half2_rn(p2, p3);
            hlo[nt] = *(uint32_t*)&h0;
            hhi[nt] = *(uint32_t*)&h1;
        }
        rs0 += __shfl_xor_sync(0xffffffffu, rs0, 1);
        rs0 += __shfl_xor_sync(0xffffffffu, rs0, 2);
        rs1 += __shfl_xor_sync(0xffffffffu, rs1, 1);
        rs1 += __shfl_xor_sync(0xffffffffu, rs1, 2);
        l0 = l0 * sc0 + rs0;
        l1 = l1 * sc1 + rs1;

#pragma unroll
        for (int nt = 0; nt < 4; nt++) {
            oacc[nt][0] *= sc0; oacc[nt][1] *= sc0;
            oacc[nt][2] *= sc1; oacc[nt][3] *= sc1;
        }

        // ---- O += P V ----
#pragma unroll
        for (int kc = 0; kc < 4; kc++) {
            const uint32_t a0 = hlo[2 * kc];
            const uint32_t a1 = hhi[2 * kc];
            const uint32_t a2 = hlo[2 * kc + 1];
            const uint32_t a3 = hhi[2 * kc + 1];
#pragma unroll
            for (int p = 0; p < 2; p++) {
                uint32_t b0, b1, b2, b3;
                const uint32_t addr = smem_u32(
                    &VsT[buf][p * 16 + rsel + ((quad >> 1) << 3)]
                             [kc * 16 + ((quad & 1) << 3)]);
                ldsm_x4(b0, b1, b2, b3, addr);
                mma_f16(oacc[2 * p][0], oacc[2 * p][1], oacc[2 * p][2], oacc[2 * p][3],
                        a0, a1, a2, a3, b0, b1);
                mma_f16(oacc[2 * p + 1][0], oacc[2 * p + 1][1], oacc[2 * p + 1][2], oacc[2 * p + 1][3],
                        a0, a1, a2, a3, b2, b3);
            }
        }
        __syncthreads();
    }

    // ---- write partials ----
    const int q0   = qt * 64 + w * 16 + g;
    const int row0 = bn * P2 + q0;
    const int row1 = row0 + 8;
    if (tig == 0) {
        g_pm[s][row0] = m0;  g_pl[s][row0] = l0;
        g_pm[s][row1] = m1;  g_pl[s][row1] = l1;
    }
    float* po0 = &g_po[s][(size_t)row0 * DV];
    float* po1 = &g_po[s][(size_t)row1 * DV];
#pragma unroll
    for (int nt = 0; nt < 4; nt++) {
        *(float2*)(po0 + nt * 8 + 2 * tig) = make_float2(oacc[nt][0], oacc[nt][1]);
        *(float2*)(po1 + nt * 8 + 2 * tig) = make_float2(oacc[nt][2], oacc[nt][3]);
    }
}

// ---------------------------------------------------------------------------
// Combine the two key-splits and normalize.
// ---------------------------------------------------------------------------
__global__ __launch_bounds__(256)
void combine_kernel(float* __restrict__ out)
{
    const int idx = blockIdx.x * 256 + threadIdx.x;
    const int row = idx >> 5;
    const int d   = idx & 31;

    const float pm0 = g_pm[0][row], pm1 = g_pm[1][row];
    const float M   = fmaxf(pm0, pm1);
    const float w0  = ex2f(pm0 - M);
    const float w1  = ex2f(pm1 - M);
    const float den = g_pl[0][row] * w0 + g_pl[1][row] * w1;
    const float v   = (g_po[0][idx] * w0 + g_po[1][idx] * w1) / den;

    const int b = row >> 13;
    const int n = (row >> 10) & 7;
    const int p = row & 1023;
    out[((size_t)(b * P2 + p) * 256) + n * DV + d] = v;
}

// ---------------------------------------------------------------------------
extern "C" void kernel_launch(void* const* d_in, const int* in_sizes, int n_in,
                              void* d_out, int out_size)
{
    const float* blob = (const float*)d_in[0];
    const float* wq   = (const float*)d_in[1];
    const float* bq   = (const float*)d_in[2];
    const float* wk   = (const float*)d_in[3];
    const float* bk   = (const float*)d_in[4];
    const float* wv   = (const float*)d_in[5];
    const float* bv   = (const float*)d_in[6];
    float* out        = (float*)d_out;

    prep_blob<<<512, 256>>>(blob);
    prep_w<<<96, 256>>>(wq, wk, wv);
    proj_gemm<<<576, 256>>>(bq, bk, bv);
    attn_tc_kernel<<<dim3(16, NH, BB * SPLIT), 128>>>();
    combine_kernel<<<(BB * NH * P2 * DV) / 256, 256>>>(out);
}

// round 7
// speedup vs baseline: 7.5589x; 1.0353x over previous
#include <cuda_runtime.h>
#include <cuda_fp16.h>
#include <math.h>
#include <stdint.h>

// Problem constants
#define BB 4
#define HH 64
#define WW 64
#define DD 256
#define NH 8
#define DK 32
#define DV 32
#define HW 4096
#define P2 1024
#define SPLIT 2
#define KSPS 2048        // keys per split

// Scratch
__device__ __half g_a16[BB * HW * DD];           //  8 MB blob f16
__device__ __half g_p16[BB * P2 * DD];           //  2 MB pooled blob f16
__device__ __half g_w16[3 * DD * DD];            // weights f16 [mode][n][k]
__device__ __half g_q[BB * NH * P2 * DK];        //  2 MB [bn][p][k] (pre-scaled 1/sqrt(K)*log2e)
__device__ __half g_k[BB * NH * HW * DK];        //  8 MB [bn][i][k]
__device__ __half g_v[BB * NH * DV * HW];        //  8 MB [bn][d][i] TRANSPOSED
__device__ float  g_po[SPLIT][BB * NH * P2 * DV];//  8 MB unnormalized partial O
__device__ float  g_pm[SPLIT][BB * NH * P2];     // partial max (log2 domain)
__device__ float  g_pl[SPLIT][BB * NH * P2];     // partial sum

#define ONES_F16X2 0x3C003C00u

// ---------------------------------------------------------------------------
__device__ __forceinline__ float ex2f(float x) {
    float r;
    asm("ex2.approx.ftz.f32 %0, %1;" : "=f"(r) : "f"(x));
    return r;
}
__device__ __forceinline__ uint32_t h2ex2(uint32_t x) {
    uint32_t r;
    asm("ex2.approx.f16x2 %0, %1;" : "=r"(r) : "r"(x));
    return r;
}
__device__ __forceinline__ void mma_f16(float& d0, float& d1, float& d2, float& d3,
                                        uint32_t a0, uint32_t a1, uint32_t a2, uint32_t a3,
                                        uint32_t b0, uint32_t b1) {
    asm volatile(
        "mma.sync.aligned.m16n8k16.row.col.f32.f16.f16.f32 "
        "{%0,%1,%2,%3}, {%4,%5,%6,%7}, {%8,%9}, {%0,%1,%2,%3};\n"
        : "+f"(d0), "+f"(d1), "+f"(d2), "+f"(d3)
        : "r"(a0), "r"(a1), "r"(a2), "r"(a3), "r"(b0), "r"(b1));
}
__device__ __forceinline__ void ldsm_x4(uint32_t& r0, uint32_t& r1, uint32_t& r2, uint32_t& r3,
                                        uint32_t a) {
    asm volatile("ldmatrix.sync.aligned.m8n8.x4.shared.b16 {%0,%1,%2,%3}, [%4];\n"
                 : "=r"(r0), "=r"(r1), "=r"(r2), "=r"(r3) : "r"(a));
}
__device__ __forceinline__ uint32_t smem_u32(const void* p) {
    return (uint32_t)__cvta_generic_to_shared(p);
}
__device__ __forceinline__ void cpa16(uint32_t s, const void* g) {
    asm volatile("cp.async.ca.shared.global [%0], [%1], 16;\n" :: "r"(s), "l"(g));
}
__device__ __forceinline__ void cpa_commit() { asm volatile("cp.async.commit_group;\n"); }
template <int N>
__device__ __forceinline__ void cpa_wait() { asm volatile("cp.async.wait_group %0;\n" :: "n"(N)); }

// ---------------------------------------------------------------------------
// Prep (merged): blk [0,512): blob f32->f16 + 2x2 maxpool.
//                blk [512,608): weights f32 [k][n] -> f16 [mode][n][k].
// ---------------------------------------------------------------------------
__global__ __launch_bounds__(256)
void prep_all(const float* __restrict__ blob,
              const float* __restrict__ wq, const float* __restrict__ wk,
              const float* __restrict__ wv)
{
    if (blockIdx.x < 512) {
        const int idx = blockIdx.x * 256 + threadIdx.x;    // 131072 total
        const int pp  = idx >> 5;
        const int c8  = (idx & 31) << 3;
        const int b  = pp >> 10, l = pp & 1023, h2 = l >> 5, w2 = l & 31;
        const int pix = (b * HH + 2 * h2) * WW + 2 * w2;
        const float* p = blob + (size_t)pix * DD + c8;

        float mx[8];
#pragma unroll
        for (int j = 0; j < 8; j++) mx[j] = -INFINITY;
        const int offs[4] = {0, DD, WW * DD, WW * DD + DD};
#pragma unroll
        for (int q = 0; q < 4; q++) {
            float4 v0 = *(const float4*)(p + offs[q]);
            float4 v1 = *(const float4*)(p + offs[q] + 4);
            float vv[8] = {v0.x, v0.y, v0.z, v0.w, v1.x, v1.y, v1.z, v1.w};
            __half hh[8];
#pragma unroll
            for (int j = 0; j < 8; j++) {
                hh[j] = __float2half_rn(vv[j]);
                mx[j] = fmaxf(mx[j], vv[j]);
            }
            const int pixq = pix + ((q >> 1) ? WW : 0) + (q & 1);
            *(uint4*)(g_a16 + (size_t)pixq * DD + c8) = *(uint4*)hh;
        }
        __half hm[8];
#pragma unroll
        for (int j = 0; j < 8; j++) hm[j] = __float2half_rn(mx[j]);
        *(uint4*)(g_p16 + (size_t)pp * DD + c8) = *(uint4*)hm;
    } else {
        const int idx = (blockIdx.x - 512) * 256 + threadIdx.x;   // 24576 total
        const int m   = idx >> 13;
        const int r   = idx & 8191;
        const int n   = r >> 5;
        const int k0  = (r & 31) << 3;
        const float* Wm = (m == 0) ? wq : (m == 1) ? wk : wv;
        __half tmp[8];
#pragma unroll
        for (int j = 0; j < 8; j++)
            tmp[j] = __float2half_rn(Wm[(size_t)(k0 + j) * DD + n]);
        *(uint4*)(g_w16 + ((size_t)m * DD + n) * DD + k0) = *(uint4*)tmp;
    }
}

// ---------------------------------------------------------------------------
// f16 tensor-core projections (unchanged from R5): 576 blocks.
// ---------------------------------------------------------------------------
__global__ __launch_bounds__(256, 2)
void proj_gemm(const float* __restrict__ bq, const float* __restrict__ bk,
               const float* __restrict__ bv)
{
    __shared__ __half As[2][128][40];
    __shared__ __half Ws[2][128][40];

    const int tid  = threadIdx.x;
    const int w    = tid >> 5;
    const int lane = tid & 31;
    const int g    = lane >> 2;
    const int tig  = lane & 3;
    const int rsel = lane & 7;
    const int quad = lane >> 3;
    const int mw   = w & 3;
    const int nw   = w >> 2;

    const int blk = blockIdx.x;
    int mode, mt, n0;
    if (blk < 64)       { mode = 0; mt = blk >> 1;          n0 = (blk & 1) << 7; }
    else if (blk < 320) { mode = 1; mt = (blk - 64) >> 1;   n0 = (blk & 1) << 7; }
    else                { mode = 2; mt = (blk - 320) >> 1;  n0 = (blk & 1) << 7; }
    const int m0 = mt << 7;

    const __half* Aptr = (mode == 0) ? g_p16 : g_a16;
    const __half* Wptr = g_w16 + (size_t)mode * DD * DD;
    const float*  bias = (mode == 0) ? bq : (mode == 1) ? bk : bv;

    auto stage = [&](int k0, int buf) {
#pragma unroll
        for (int t = 0; t < 2; t++) {
            const int i   = tid + 256 * t;
            const int row = i >> 2;
            const int c   = i & 3;
            cpa16(smem_u32(&As[buf][row][c * 8]), Aptr + (size_t)(m0 + row) * DD + k0 + c * 8);
            cpa16(smem_u32(&Ws[buf][row][c * 8]), Wptr + (size_t)(n0 + row) * DD + k0 + c * 8);
        }
    };

    float acc[2][8][4];
#pragma unroll
    for (int t = 0; t < 2; t++)
#pragma unroll
        for (int nt = 0; nt < 8; nt++)
#pragma unroll
            for (int j = 0; j < 4; j++) acc[t][nt][j] = 0.0f;

    stage(0, 0);
    cpa_commit();

    for (int ks = 0; ks < 8; ks++) {
        const int buf = ks & 1;
        if (ks + 1 < 8) {
            stage((ks + 1) * 32, buf ^ 1);
            cpa_commit();
            cpa_wait<1>();
        } else {
            cpa_wait<0>();
        }
        __syncthreads();

#pragma unroll
        for (int kc = 0; kc < 2; kc++) {
            uint32_t af[2][4];
#pragma unroll
            for (int t = 0; t < 2; t++) {
                const uint32_t addr = smem_u32(
                    &As[buf][mw * 32 + t * 16 + rsel + ((quad & 1) << 3)]
                            [kc * 16 + ((quad >> 1) << 3)]);
                ldsm_x4(af[t][0], af[t][1], af[t][2], af[t][3], addr);
            }
#pragma unroll
            for (int p = 0; p < 4; p++) {
                uint32_t b0, b1, b2, b3;
                const uint32_t addr = smem_u32(
                    &Ws[buf][nw * 64 + p * 16 + rsel + ((quad >> 1) << 3)]
                            [kc * 16 + ((quad & 1) << 3)]);
                ldsm_x4(b0, b1, b2, b3, addr);
#pragma unroll
                for (int t = 0; t < 2; t++) {
                    mma_f16(acc[t][2 * p][0], acc[t][2 * p][1], acc[t][2 * p][2], acc[t][2 * p][3],
                            af[t][0], af[t][1], af[t][2], af[t][3], b0, b1);
                    mma_f16(acc[t][2 * p + 1][0], acc[t][2 * p + 1][1], acc[t][2 * p + 1][2], acc[t][2 * p + 1][3],
                            af[t][0], af[t][1], af[t][2], af[t][3], b2, b3);
                }
            }
        }
        __syncthreads();
    }

    const float QSCL = 0.17677669529663687f * 1.4426950408889634f;
#pragma unroll
    for (int t = 0; t < 2; t++) {
#pragma unroll
        for (int nt = 0; nt < 8; nt++) {
#pragma unroll
            for (int half = 0; half < 2; half++) {
                const int r = m0 + mw * 32 + t * 16 + g + half * 8;
#pragma unroll
                for (int j = 0; j < 2; j++) {
                    const int c = n0 + nw * 64 + nt * 8 + 2 * tig + j;
                    float val   = acc[t][nt][half * 2 + j] + __ldg(bias + c);
                    const int n = c >> 5;
                    const int d = c & 31;
                    if (mode == 0) {
                        val *= QSCL;
                        const int b = r >> 10, p2 = r & 1023;
                        g_q[(((b * NH + n) * P2) + p2) * DK + d] = __float2half_rn(val);
                    } else if (mode == 1) {
                        const int b = r >> 12, ii = r & 4095;
                        g_k[(((b * NH + n) * HW) + ii) * DK + d] = __float2half_rn(val);
                    } else {
                        val = val / (1.0f + __expf(-val));
                        const int b = r >> 12, ii = r & 4095;
                        g_v[(((size_t)(b * NH + n) * DV) + d) * HW + ii] = __float2half_rn(val);
                    }
                }
            }
        }
    }
}

// ---------------------------------------------------------------------------
// Split-K fp16 flash attention.
// Block: 8 warps / 256 thr / 128 queries; 2048 keys; 64-key tiles.
// ex2.f16x2 softmax; row-sum l via ones-fragment MMA (free on tensor pipe).
// ---------------------------------------------------------------------------
__global__ __launch_bounds__(256)
void attn_tc_kernel()
{
    __shared__ __half Qs[128][40];
    __shared__ __half Ks[2][64][40];
    __shared__ __half VsT[2][32][72];

    const int tid  = threadIdx.x;
    const int w    = tid >> 5;            // 0..7
    const int lane = tid & 31;
    const int g    = lane >> 2;
    const int tig  = lane & 3;
    const int rsel = lane & 7;
    const int quad = lane >> 3;

    const int qt = blockIdx.x;            // 0..7 (128 queries each)
    const int n  = blockIdx.y;
    const int z  = blockIdx.z;
    const int b  = z >> 1;
    const int s  = z & 1;
    const int bn = b * NH + n;

    const __half* qglob = g_q + (size_t)(bn * P2 + qt * 128) * DK;
    const __half* kglob = g_k + ((size_t)bn * HW + s * KSPS) * DK;
    const __half* vglob = g_v + (size_t)bn * DV * HW + s * KSPS;

    // stage Q once: 128 rows x 64B = 512 x 16B
#pragma unroll
    for (int t = 0; t < 2; t++) {
        const int i   = tid + 256 * t;
        const int row = i >> 2;
        const int c   = i & 3;
        *(float4*)&Qs[row][c * 8] = *(const float4*)(qglob + row * DK + c * 8);
    }

    auto stage = [&](int j0, int buf) {
        {   // K: 64 rows x 64B = 256 chunks
            const int row = tid >> 2;
            const int c   = tid & 3;
            cpa16(smem_u32(&Ks[buf][row][c * 8]), kglob + (size_t)(j0 + row) * DK + c * 8);
        }
        {   // V^T: 32 rows x 128B = 256 chunks
            const int row = tid >> 3;
            const int c   = tid & 7;
            cpa16(smem_u32(&VsT[buf][row][c * 8]), vglob + (size_t)row * HW + j0 + c * 8);
        }
    };

    stage(0, 0);
    cpa_commit();
    __syncthreads();

    uint32_t Qf[2][4];
    const int r0 = w * 16 + g;
#pragma unroll
    for (int kc = 0; kc < 2; kc++) {
        Qf[kc][0] = *(const uint32_t*)&Qs[r0    ][kc * 16 + 2 * tig    ];
        Qf[kc][1] = *(const uint32_t*)&Qs[r0 + 8][kc * 16 + 2 * tig    ];
        Qf[kc][2] = *(const uint32_t*)&Qs[r0    ][kc * 16 + 2 * tig + 8];
        Qf[kc][3] = *(const uint32_t*)&Qs[r0 + 8][kc * 16 + 2 * tig + 8];
    }

    float m0 = -INFINITY, m1 = -INFINITY;
    float lacc[4] = {0.0f, 0.0f, 0.0f, 0.0f};
    float oacc[4][4];
#pragma unroll
    for (int i = 0; i < 4; i++)
#pragma unroll
        for (int j = 0; j < 4; j++) oacc[i][j] = 0.0f;

    for (int it = 0; it < KSPS / 64; it++) {
        const int buf = it & 1;
        if (it + 1 < KSPS / 64) {
            stage((it + 1) * 64, buf ^ 1);
            cpa_commit();
            cpa_wait<1>();
        } else {
            cpa_wait<0>();
        }
        __syncthreads();

        // ---- S = Q K^T ----
        float sacc[8][4];
#pragma unroll
        for (int nt = 0; nt < 8; nt++)
#pragma unroll
            for (int j = 0; j < 4; j++) sacc[nt][j] = 0.0f;

#pragma unroll
        for (int kc = 0; kc < 2; kc++) {
#pragma unroll
            for (int p = 0; p < 4; p++) {
                uint32_t b0, b1, b2, b3;
                const uint32_t addr = smem_u32(
                    &Ks[buf][p * 16 + rsel + ((quad >> 1) << 3)]
                            [kc * 16 + ((quad & 1) << 3)]);
                ldsm_x4(b0, b1, b2, b3, addr);
                mma_f16(sacc[2 * p][0], sacc[2 * p][1], sacc[2 * p][2], sacc[2 * p][3],
                        Qf[kc][0], Qf[kc][1], Qf[kc][2], Qf[kc][3], b0, b1);
                mma_f16(sacc[2 * p + 1][0], sacc[2 * p + 1][1], sacc[2 * p + 1][2], sacc[2 * p + 1][3],
                        Qf[kc][0], Qf[kc][1], Qf[kc][2], Qf[kc][3], b2, b3);
            }
        }

        // ---- online softmax (exp2 domain, half2 MUFU) ----
        float mx0 = -INFINITY, mx1 = -INFINITY;
#pragma unroll
        for (int nt = 0; nt < 8; nt++) {
            mx0 = fmaxf(mx0, fmaxf(sacc[nt][0], sacc[nt][1]));
            mx1 = fmaxf(mx1, fmaxf(sacc[nt][2], sacc[nt][3]));
        }
        mx0 = fmaxf(mx0, __shfl_xor_sync(0xffffffffu, mx0, 1));
        mx0 = fmaxf(mx0, __shfl_xor_sync(0xffffffffu, mx0, 2));
        mx1 = fmaxf(mx1, __shfl_xor_sync(0xffffffffu, mx1, 1));
        mx1 = fmaxf(mx1, __shfl_xor_sync(0xffffffffu, mx1, 2));

        const float nm0 = fmaxf(m0, mx0);
        const float nm1 = fmaxf(m1, mx1);
        const float sc0 = ex2f(m0 - nm0);   // 0 on first tile
        const float sc1 = ex2f(m1 - nm1);
        m0 = nm0; m1 = nm1;

        uint32_t hlo[8], hhi[8];
#pragma unroll
        for (int nt = 0; nt < 8; nt++) {
            __half2 d0 = __floats2half2_rn(sacc[nt][0] - nm0, sacc[nt][1] - nm0);
            __half2 d1 = __floats2half2_rn(sacc[nt][2] - nm1, sacc[nt][3] - nm1);
            hlo[nt] = h2ex2(*(uint32_t*)&d0);
            hhi[nt] = h2ex2(*(uint32_t*)&d1);
        }

        // rescale accumulators (rows g -> sc0, rows g+8 -> sc1)
#pragma unroll
        for (int nt = 0; nt < 4; nt++) {
            oacc[nt][0] *= sc0; oacc[nt][1] *= sc0;
            oacc[nt][2] *= sc1; oacc[nt][3] *= sc1;
        }
        lacc[0] *= sc0; lacc[1] *= sc0;
        lacc[2] *= sc1; lacc[3] *= sc1;

        // ---- O += P V ; l += P @ 1 (ones-fragment mma) ----
#pragma unroll
        for (int kc = 0; kc < 4; kc++) {
            const uint32_t a0 = hlo[2 * kc];
            const uint32_t a1 = hhi[2 * kc];
            const uint32_t a2 = hlo[2 * kc + 1];
            const uint32_t a3 = hhi[2 * kc + 1];
            mma_f16(lacc[0], lacc[1], lacc[2], lacc[3],
                    a0, a1, a2, a3, ONES_F16X2, ONES_F16X2);
#pragma unroll
            for (int p = 0; p < 2; p++) {
                uint32_t b0, b1, b2, b3;
                const uint32_t addr = smem_u32(
                    &VsT[buf][p * 16 + rsel + ((quad >> 1) << 3)]
                             [kc * 16 + ((quad & 1) << 3)]);
                ldsm_x4(b0, b1, b2, b3, addr);
                mma_f16(oacc[2 * p][0], oacc[2 * p][1], oacc[2 * p][2], oacc[2 * p][3],
                        a0, a1, a2, a3, b0, b1);
                mma_f16(oacc[2 * p + 1][0], oacc[2 * p + 1][1], oacc[2 * p + 1][2], oacc[2 * p + 1][3],
                        a0, a1, a2, a3, b2, b3);
            }
        }
        __syncthreads();
    }

    // ---- write partials (unnormalized) ----
    const int q0   = qt * 128 + w * 16 + g;
    const int row0 = bn * P2 + q0;
    const int row1 = row0 + 8;
    if (tig == 0) {
        g_pm[s][row0] = m0;  g_pl[s][row0] = lacc[0];
        g_pm[s][row1] = m1;  g_pl[s][row1] = lacc[2];
    }
    float* po0 = &g_po[s][(size_t)row0 * DV];
    float* po1 = &g_po[s][(size_t)row1 * DV];
#pragma unroll
    for (int nt = 0; nt < 4; nt++) {
        *(float2*)(po0 + nt * 8 + 2 * tig) = make_float2(oacc[nt][0], oacc[nt][1]);
        *(float2*)(po1 + nt * 8 + 2 * tig) = make_float2(oacc[nt][2], oacc[nt][3]);
    }
}

// ---------------------------------------------------------------------------
// Combine the two key-splits and normalize.
// ---------------------------------------------------------------------------
__global__ __launch_bounds__(256)
void combine_kernel(float* __restrict__ out)
{
    const int idx = blockIdx.x * 256 + threadIdx.x;
    const int row = idx >> 5;
    const int d   = idx & 31;

    const float pm0 = g_pm[0][row], pm1 = g_pm[1][row];
    const float M   = fmaxf(pm0, pm1);
    const float w0  = ex2f(pm0 - M);
    const float w1  = ex2f(pm1 - M);
    const float den = g_pl[0][row] * w0 + g_pl[1][row] * w1;
    const float v   = (g_po[0][idx] * w0 + g_po[1][idx] * w1) / den;

    const int b = row >> 13;
    const int n = (row >> 10) & 7;
    const int p = row & 1023;
    out[((size_t)(b * P2 + p) * 256) + n * DV + d] = v;
}

// ---------------------------------------------------------------------------
extern "C" void kernel_launch(void* const* d_in, const int* in_sizes, int n_in,
                              void* d_out, int out_size)
{
    const float* blob = (const float*)d_in[0];
    const float* wq   = (const float*)d_in[1];
    const float* bq   = (const float*)d_in[2];
    const float* wk   = (const float*)d_in[3];
    const float* bk   = (const float*)d_in[4];
    const float* wv   = (const float*)d_in[5];
    const float* bv   = (const float*)d_in[6];
    float* out        = (float*)d_out;

    prep_all<<<608, 256>>>(blob, wq, wk, wv);
    proj_gemm<<<576, 256>>>(bq, bk, bv);
    attn_tc_kernel<<<dim3(8, NH, BB * SPLIT), 256>>>();
    combine_kernel<<<(BB * NH * P2 * DV) / 256, 256>>>(out);
}

// round 8
// speedup vs baseline: 7.7022x; 1.0190x over previous
#include <cuda_runtime.h>
#include <cuda_fp16.h>
#include <math.h>
#include <stdint.h>

// Problem constants
#define BB 4
#define HH 64
#define WW 64
#define DD 256
#define NH 8
#define DK 32
#define DV 32
#define HW 4096
#define P2 1024
#define SPLIT 2
#define KSPS 2048        // keys per split

// Scratch
__device__ __half g_a16[BB * HW * DD];           //  8 MB blob f16
__device__ __half g_p16[BB * P2 * DD];           //  2 MB pooled blob f16
__device__ __half g_w16[3 * DD * DD];            // weights f16 [mode][n][k]
__device__ __half g_q[BB * NH * P2 * DK];        //  2 MB [bn][p][k] (pre-scaled 1/sqrt(K)*log2e)
__device__ __half g_k[BB * NH * HW * DK];        //  8 MB [bn][i][k]
__device__ __half g_v[BB * NH * DV * HW];        //  8 MB [bn][d][i] TRANSPOSED
__device__ float  g_po[SPLIT][BB * NH * P2 * DV];//  8 MB unnormalized partial O
__device__ float  g_pm[SPLIT][BB * NH * P2];     // partial max (log2 domain)
__device__ float  g_pl[SPLIT][BB * NH * P2];     // partial sum

#define ONES_F16X2 0x3C003C00u

// ---------------------------------------------------------------------------
__device__ __forceinline__ float ex2f(float x) {
    float r;
    asm("ex2.approx.ftz.f32 %0, %1;" : "=f"(r) : "f"(x));
    return r;
}
__device__ __forceinline__ uint32_t h2ex2(uint32_t x) {
    uint32_t r;
    asm("ex2.approx.f16x2 %0, %1;" : "=r"(r) : "r"(x));
    return r;
}
__device__ __forceinline__ void mma_f16(float& d0, float& d1, float& d2, float& d3,
                                        uint32_t a0, uint32_t a1, uint32_t a2, uint32_t a3,
                                        uint32_t b0, uint32_t b1) {
    asm volatile(
        "mma.sync.aligned.m16n8k16.row.col.f32.f16.f16.f32 "
        "{%0,%1,%2,%3}, {%4,%5,%6,%7}, {%8,%9}, {%0,%1,%2,%3};\n"
        : "+f"(d0), "+f"(d1), "+f"(d2), "+f"(d3)
        : "r"(a0), "r"(a1), "r"(a2), "r"(a3), "r"(b0), "r"(b1));
}
__device__ __forceinline__ void ldsm_x4(uint32_t& r0, uint32_t& r1, uint32_t& r2, uint32_t& r3,
                                        uint32_t a) {
    asm volatile("ldmatrix.sync.aligned.m8n8.x4.shared.b16 {%0,%1,%2,%3}, [%4];\n"
                 : "=r"(r0), "=r"(r1), "=r"(r2), "=r"(r3) : "r"(a));
}
__device__ __forceinline__ uint32_t smem_u32(const void* p) {
    return (uint32_t)__cvta_generic_to_shared(p);
}
__device__ __forceinline__ void cpa16(uint32_t s, const void* g) {
    asm volatile("cp.async.ca.shared.global [%0], [%1], 16;\n" :: "r"(s), "l"(g));
}
__device__ __forceinline__ void cpa_commit() { asm volatile("cp.async.commit_group;\n"); }
template <int N>
__device__ __forceinline__ void cpa_wait() { asm volatile("cp.async.wait_group %0;\n" :: "n"(N)); }

// ---------------------------------------------------------------------------
// Prep (merged): blk [0,512): blob f32->f16 + 2x2 maxpool.
//                blk [512,608): weights f32 [k][n] -> f16 [mode][n][k].
// ---------------------------------------------------------------------------
__global__ __launch_bounds__(256)
void prep_all(const float* __restrict__ blob,
              const float* __restrict__ wq, const float* __restrict__ wk,
              const float* __restrict__ wv)
{
    if (blockIdx.x < 512) {
        const int idx = blockIdx.x * 256 + threadIdx.x;    // 131072 total
        const int pp  = idx >> 5;
        const int c8  = (idx & 31) << 3;
        const int b  = pp >> 10, l = pp & 1023, h2 = l >> 5, w2 = l & 31;
        const int pix = (b * HH + 2 * h2) * WW + 2 * w2;
        const float* p = blob + (size_t)pix * DD + c8;

        float mx[8];
#pragma unroll
        for (int j = 0; j < 8; j++) mx[j] = -INFINITY;
        const int offs[4] = {0, DD, WW * DD, WW * DD + DD};
#pragma unroll
        for (int q = 0; q < 4; q++) {
            float4 v0 = *(const float4*)(p + offs[q]);
            float4 v1 = *(const float4*)(p + offs[q] + 4);
            float vv[8] = {v0.x, v0.y, v0.z, v0.w, v1.x, v1.y, v1.z, v1.w};
            __half hh[8];
#pragma unroll
            for (int j = 0; j < 8; j++) {
                hh[j] = __float2half_rn(vv[j]);
                mx[j] = fmaxf(mx[j], vv[j]);
            }
            const int pixq = pix + ((q >> 1) ? WW : 0) + (q & 1);
            *(uint4*)(g_a16 + (size_t)pixq * DD + c8) = *(uint4*)hh;
        }
        __half hm[8];
#pragma unroll
        for (int j = 0; j < 8; j++) hm[j] = __float2half_rn(mx[j]);
        *(uint4*)(g_p16 + (size_t)pp * DD + c8) = *(uint4*)hm;
    } else {
        const int idx = (blockIdx.x - 512) * 256 + threadIdx.x;   // 24576 total
        const int m   = idx >> 13;
        const int r   = idx & 8191;
        const int n   = r >> 5;
        const int k0  = (r & 31) << 3;
        const float* Wm = (m == 0) ? wq : (m == 1) ? wk : wv;
        __half tmp[8];
#pragma unroll
        for (int j = 0; j < 8; j++)
            tmp[j] = __float2half_rn(Wm[(size_t)(k0 + j) * DD + n]);
        *(uint4*)(g_w16 + ((size_t)m * DD + n) * DD + k0) = *(uint4*)tmp;
    }
}

// ---------------------------------------------------------------------------
// f16 tensor-core projections: 576 blocks (unchanged).
// ---------------------------------------------------------------------------
__global__ __launch_bounds__(256, 2)
void proj_gemm(const float* __restrict__ bq, const float* __restrict__ bk,
               const float* __restrict__ bv)
{
    __shared__ __half As[2][128][40];
    __shared__ __half Ws[2][128][40];

    const int tid  = threadIdx.x;
    const int w    = tid >> 5;
    const int lane = tid & 31;
    const int g    = lane >> 2;
    const int tig  = lane & 3;
    const int rsel = lane & 7;
    const int quad = lane >> 3;
    const int mw   = w & 3;
    const int nw   = w >> 2;

    const int blk = blockIdx.x;
    int mode, mt, n0;
    if (blk < 64)       { mode = 0; mt = blk >> 1;          n0 = (blk & 1) << 7; }
    else if (blk < 320) { mode = 1; mt = (blk - 64) >> 1;   n0 = (blk & 1) << 7; }
    else                { mode = 2; mt = (blk - 320) >> 1;  n0 = (blk & 1) << 7; }
    const int m0 = mt << 7;

    const __half* Aptr = (mode == 0) ? g_p16 : g_a16;
    const __half* Wptr = g_w16 + (size_t)mode * DD * DD;
    const float*  bias = (mode == 0) ? bq : (mode == 1) ? bk : bv;

    auto stage = [&](int k0, int buf) {
#pragma unroll
        for (int t = 0; t < 2; t++) {
            const int i   = tid + 256 * t;
            const int row = i >> 2;
            const int c   = i & 3;
            cpa16(smem_u32(&As[buf][row][c * 8]), Aptr + (size_t)(m0 + row) * DD + k0 + c * 8);
            cpa16(smem_u32(&Ws[buf][row][c * 8]), Wptr + (size_t)(n0 + row) * DD + k0 + c * 8);
        }
    };

    float acc[2][8][4];
#pragma unroll
    for (int t = 0; t < 2; t++)
#pragma unroll
        for (int nt = 0; nt < 8; nt++)
#pragma unroll
            for (int j = 0; j < 4; j++) acc[t][nt][j] = 0.0f;

    stage(0, 0);
    cpa_commit();

    for (int ks = 0; ks < 8; ks++) {
        const int buf = ks & 1;
        if (ks + 1 < 8) {
            stage((ks + 1) * 32, buf ^ 1);
            cpa_commit();
            cpa_wait<1>();
        } else {
            cpa_wait<0>();
        }
        __syncthreads();

#pragma unroll
        for (int kc = 0; kc < 2; kc++) {
            uint32_t af[2][4];
#pragma unroll
            for (int t = 0; t < 2; t++) {
                const uint32_t addr = smem_u32(
                    &As[buf][mw * 32 + t * 16 + rsel + ((quad & 1) << 3)]
                            [kc * 16 + ((quad >> 1) << 3)]);
                ldsm_x4(af[t][0], af[t][1], af[t][2], af[t][3], addr);
            }
#pragma unroll
            for (int p = 0; p < 4; p++) {
                uint32_t b0, b1, b2, b3;
                const uint32_t addr = smem_u32(
                    &Ws[buf][nw * 64 + p * 16 + rsel + ((quad >> 1) << 3)]
                            [kc * 16 + ((quad & 1) << 3)]);
                ldsm_x4(b0, b1, b2, b3, addr);
#pragma unroll
                for (int t = 0; t < 2; t++) {
                    mma_f16(acc[t][2 * p][0], acc[t][2 * p][1], acc[t][2 * p][2], acc[t][2 * p][3],
                            af[t][0], af[t][1], af[t][2], af[t][3], b0, b1);
                    mma_f16(acc[t][2 * p + 1][0], acc[t][2 * p + 1][1], acc[t][2 * p + 1][2], acc[t][2 * p + 1][3],
                            af[t][0], af[t][1], af[t][2], af[t][3], b2, b3);
                }
            }
        }
        __syncthreads();
    }

    const float QSCL = 0.17677669529663687f * 1.4426950408889634f;
#pragma unroll
    for (int t = 0; t < 2; t++) {
#pragma unroll
        for (int nt = 0; nt < 8; nt++) {
#pragma unroll
            for (int half = 0; half < 2; half++) {
                const int r = m0 + mw * 32 + t * 16 + g + half * 8;
#pragma unroll
                for (int j = 0; j < 2; j++) {
                    const int c = n0 + nw * 64 + nt * 8 + 2 * tig + j;
                    float val   = acc[t][nt][half * 2 + j] + __ldg(bias + c);
                    const int n = c >> 5;
                    const int d = c & 31;
                    if (mode == 0) {
                        val *= QSCL;
                        const int b = r >> 10, p2 = r & 1023;
                        g_q[(((b * NH + n) * P2) + p2) * DK + d] = __float2half_rn(val);
                    } else if (mode == 1) {
                        const int b = r >> 12, ii = r & 4095;
                        g_k[(((b * NH + n) * HW) + ii) * DK + d] = __float2half_rn(val);
                    } else {
                        val = val / (1.0f + __expf(-val));
                        const int b = r >> 12, ii = r & 4095;
                        g_v[(((size_t)(b * NH + n) * DV) + d) * HW + ii] = __float2half_rn(val);
                    }
                }
            }
        }
    }
}

// ---------------------------------------------------------------------------
// Split-K fp16 flash attention.
// Block: 8 warps / 256 thr / 128 queries; 2048 keys; 64-key tiles.
// 3-stage cp.async pipeline (ONE barrier per tile); warp-uniform lazy max;
// row-sum l via ones-fragment MMA.
// ---------------------------------------------------------------------------
__global__ __launch_bounds__(256)
void attn_tc_kernel()
{
    __shared__ __half Qs[128][40];
    __shared__ __half Ks[3][64][40];
    __shared__ __half VsT[3][32][72];

    const int tid  = threadIdx.x;
    const int w    = tid >> 5;            // 0..7
    const int lane = tid & 31;
    const int g    = lane >> 2;
    const int tig  = lane & 3;
    const int rsel = lane & 7;
    const int quad = lane >> 3;

    const int qt = blockIdx.x;            // 0..7 (128 queries each)
    const int n  = blockIdx.y;
    const int z  = blockIdx.z;
    const int b  = z >> 1;
    const int s  = z & 1;
    const int bn = b * NH + n;

    const __half* qglob = g_q + (size_t)(bn * P2 + qt * 128) * DK;
    const __half* kglob = g_k + ((size_t)bn * HW + s * KSPS) * DK;
    const __half* vglob = g_v + (size_t)bn * DV * HW + s * KSPS;

    // stage Q once: 128 rows x 64B = 512 x 16B
#pragma unroll
    for (int t = 0; t < 2; t++) {
        const int i   = tid + 256 * t;
        const int row = i >> 2;
        const int c   = i & 3;
        *(float4*)&Qs[row][c * 8] = *(const float4*)(qglob + row * DK + c * 8);
    }

    auto stage = [&](int j0, int buf) {
        {   // K: 64 rows x 64B = 256 chunks
            const int row = tid >> 2;
            const int c   = tid & 3;
            cpa16(smem_u32(&Ks[buf][row][c * 8]), kglob + (size_t)(j0 + row) * DK + c * 8);
        }
        {   // V^T: 32 rows x 128B = 256 chunks
            const int row = tid >> 3;
            const int c   = tid & 7;
            cpa16(smem_u32(&VsT[buf][row][c * 8]), vglob + (size_t)row * HW + j0 + c * 8);
        }
    };

    const int NT = KSPS / 64;             // 32
    stage(0, 0);   cpa_commit();
    stage(64, 1);  cpa_commit();
    __syncthreads();                      // Qs visible

    uint32_t Qf[2][4];
    const int r0 = w * 16 + g;
#pragma unroll
    for (int kc = 0; kc < 2; kc++) {
        Qf[kc][0] = *(const uint32_t*)&Qs[r0    ][kc * 16 + 2 * tig    ];
        Qf[kc][1] = *(const uint32_t*)&Qs[r0 + 8][kc * 16 + 2 * tig    ];
        Qf[kc][2] = *(const uint32_t*)&Qs[r0    ][kc * 16 + 2 * tig + 8];
        Qf[kc][3] = *(const uint32_t*)&Qs[r0 + 8][kc * 16 + 2 * tig + 8];
    }

    float m = -INFINITY;                  // warp-uniform running max (log2 domain)
    float lacc[4] = {0.0f, 0.0f, 0.0f, 0.0f};
    float oacc[4][4];
#pragma unroll
    for (int i = 0; i < 4; i++)
#pragma unroll
        for (int j = 0; j < 4; j++) oacc[i][j] = 0.0f;

    for (int it = 0; it < NT; it++) {
        const int buf = it % 3;
        if (it == NT - 1) cpa_wait<0>(); else cpa_wait<1>();
        __syncthreads();                  // ONE barrier per tile

        // ---- S = Q K^T ----
        float sacc[8][4];
#pragma unroll
        for (int nt = 0; nt < 8; nt++)
#pragma unroll
            for (int j = 0; j < 4; j++) sacc[nt][j] = 0.0f;

#pragma unroll
        for (int kc = 0; kc < 2; kc++) {
#pragma unroll
            for (int p = 0; p < 4; p++) {
                uint32_t b0, b1, b2, b3;
                const uint32_t addr = smem_u32(
                    &Ks[buf][p * 16 + rsel + ((quad >> 1) << 3)]
                            [kc * 16 + ((quad & 1) << 3)]);
                ldsm_x4(b0, b1, b2, b3, addr);
                mma_f16(sacc[2 * p][0], sacc[2 * p][1], sacc[2 * p][2], sacc[2 * p][3],
                        Qf[kc][0], Qf[kc][1], Qf[kc][2], Qf[kc][3], b0, b1);
                mma_f16(sacc[2 * p + 1][0], sacc[2 * p + 1][1], sacc[2 * p + 1][2], sacc[2 * p + 1][3],
                        Qf[kc][0], Qf[kc][1], Qf[kc][2], Qf[kc][3], b2, b3);
            }
        }

        // ---- warp-uniform lazy max ----
        float mx = -INFINITY;
#pragma unroll
        for (int nt = 0; nt < 8; nt++) {
            mx = fmaxf(mx, fmaxf(fmaxf(sacc[nt][0], sacc[nt][1]),
                                 fmaxf(sacc[nt][2], sacc[nt][3])));
        }
#pragma unroll
        for (int d = 16; d >= 1; d >>= 1)
            mx = fmaxf(mx, __shfl_xor_sync(0xffffffffu, mx, d));

        if (mx > m) {                     // warp-uniform branch; rare after warmup
            const float sc = ex2f(m - mx);   // 0 on first tile
            m = mx;
#pragma unroll
            for (int nt = 0; nt < 4; nt++) {
                oacc[nt][0] *= sc; oacc[nt][1] *= sc;
                oacc[nt][2] *= sc; oacc[nt][3] *= sc;
            }
            lacc[0] *= sc; lacc[1] *= sc; lacc[2] *= sc; lacc[3] *= sc;
        }

        // ---- P = 2^(S - m) in f16 ----
        uint32_t hlo[8], hhi[8];
#pragma unroll
        for (int nt = 0; nt < 8; nt++) {
            __half2 d0 = __floats2half2_rn(sacc[nt][0] - m, sacc[nt][1] - m);
            __half2 d1 = __floats2half2_rn(sacc[nt][2] - m, sacc[nt][3] - m);
            hlo[nt] = h2ex2(*(uint32_t*)&d0);
            hhi[nt] = h2ex2(*(uint32_t*)&d1);
        }

        // ---- O += P V ; l += P @ 1 ----
#pragma unroll
        for (int kc = 0; kc < 4; kc++) {
            const uint32_t a0 = hlo[2 * kc];
            const uint32_t a1 = hhi[2 * kc];
            const uint32_t a2 = hlo[2 * kc + 1];
            const uint32_t a3 = hhi[2 * kc + 1];
            mma_f16(lacc[0], lacc[1], lacc[2], lacc[3],
                    a0, a1, a2, a3, ONES_F16X2, ONES_F16X2);
#pragma unroll
            for (int p = 0; p < 2; p++) {
                uint32_t b0, b1, b2, b3;
                const uint32_t addr = smem_u32(
                    &VsT[buf][p * 16 + rsel + ((quad >> 1) << 3)]
                             [kc * 16 + ((quad & 1) << 3)]);
                ldsm_x4(b0, b1, b2, b3, addr);
                mma_f16(oacc[2 * p][0], oacc[2 * p][1], oacc[2 * p][2], oacc[2 * p][3],
                        a0, a1, a2, a3, b0, b1);
                mma_f16(oacc[2 * p + 1][0], oacc[2 * p + 1][1], oacc[2 * p + 1][2], oacc[2 * p + 1][3],
                        a0, a1, a2, a3, b2, b3);
            }
        }

        // stage tile it+2 into buffer (it+2)%3 (last read at it-1, protected
        // by this iteration's top barrier)
        if (it + 2 < NT) {
            stage((it + 2) * 64, (it + 2) % 3);
            cpa_commit();
        }
    }

    // ---- write partials (unnormalized) ----
    const int q0   = qt * 128 + w * 16 + g;
    const int row0 = bn * P2 + q0;
    const int row1 = row0 + 8;
    if (tig == 0) {
        g_pm[s][row0] = m;   g_pl[s][row0] = lacc[0];
        g_pm[s][row1] = m;   g_pl[s][row1] = lacc[2];
    }
    float* po0 = &g_po[s][(size_t)row0 * DV];
    float* po1 = &g_po[s][(size_t)row1 * DV];
#pragma unroll
    for (int nt = 0; nt < 4; nt++) {
        *(float2*)(po0 + nt * 8 + 2 * tig) = make_float2(oacc[nt][0], oacc[nt][1]);
        *(float2*)(po1 + nt * 8 + 2 * tig) = make_float2(oacc[nt][2], oacc[nt][3]);
    }
}

// ---------------------------------------------------------------------------
// Combine the two key-splits and normalize (8 elems/thread, float4).
// ---------------------------------------------------------------------------
__global__ __launch_bounds__(256)
void combine_kernel(float* __restrict__ out)
{
    const int idx = blockIdx.x * 256 + threadIdx.x;    // 131072 total
    const int row = idx >> 2;                          // bn*P2 + p
    const int d0  = (idx & 3) << 3;

    const float pm0 = g_pm[0][row], pm1 = g_pm[1][row];
    const float M   = fmaxf(pm0, pm1);
    const float w0  = ex2f(pm0 - M);
    const float w1  = ex2f(pm1 - M);
    const float inv = 1.0f / (g_pl[0][row] * w0 + g_pl[1][row] * w1);
    const float c0  = w0 * inv;
    const float c1  = w1 * inv;

    const float4* a = (const float4*)&g_po[0][(size_t)row * DV + d0];
    const float4* c = (const float4*)&g_po[1][(size_t)row * DV + d0];

    const int b = row >> 13;
    const int n = (row >> 10) & 7;
    const int p = row & 1023;
    float4* o = (float4*)(out + ((size_t)(b * P2 + p) * 256) + n * DV + d0);

#pragma unroll
    for (int t = 0; t < 2; t++) {
        float4 x = a[t], y = c[t];
        float4 r;
        r.x = x.x * c0 + y.x * c1;
        r.y = x.y * c0 + y.y * c1;
        r.z = x.z * c0 + y.z * c1;
        r.w = x.w * c0 + y.w * c1;
        o[t] = r;
    }
}

// ---------------------------------------------------------------------------
extern "C" void kernel_launch(void* const* d_in, const int* in_sizes, int n_in,
                              void* d_out, int out_size)
{
    const float* blob = (const float*)d_in[0];
    const float* wq   = (const float*)d_in[1];
    const float* bq   = (const float*)d_in[2];
    const float* wk   = (const float*)d_in[3];
    const float* bk   = (const float*)d_in[4];
    const float* wv   = (const float*)d_in[5];
    const float* bv   = (const float*)d_in[6];
    float* out        = (float*)d_out;

    prep_all<<<608, 256>>>(blob, wq, wk, wv);
    proj_gemm<<<576, 256>>>(bq, bk, bv);
    attn_tc_kernel<<<dim3(8, NH, BB * SPLIT), 256>>>();
    combine_kernel<<<512, 256>>>(out);
}

// round 9
// speedup vs baseline: 8.3345x; 1.0821x over previous
#include <cuda_runtime.h>
#include <cuda_fp16.h>
#include <math.h>
#include <stdint.h>

// Problem constants
#define BB 4
#define HH 64
#define WW 64
#define DD 256
#define NH 8
#define DK 32
#define DV 32
#define HW 4096
#define P2 1024
#define SPLIT 4
#define KSPS 1024        // keys per split

// Scratch
__device__ __half g_a16[BB * HW * DD];           //  8 MB blob f16
__device__ __half g_p16[BB * P2 * DD];           //  2 MB pooled blob f16
__device__ __half g_w16[3 * DD * DD];            // weights f16 [mode][n][k]
__device__ __half g_q[BB * NH * P2 * DK];        //  2 MB [bn][p][k] (pre-scaled 1/sqrt(K)*log2e)
__device__ __half g_k[BB * NH * HW * DK];        //  8 MB [bn][i][k]
__device__ __half g_v[BB * NH * DV * HW];        //  8 MB [bn][d][i] TRANSPOSED
__device__ float  g_po[SPLIT][BB * NH * P2 * DV];// 16 MB unnormalized partial O
__device__ float  g_pm[SPLIT][BB * NH * P2];     // partial max (log2 domain)
__device__ float  g_pl[SPLIT][BB * NH * P2];     // partial sum

#define ONES_F16X2 0x3C003C00u

// ---------------------------------------------------------------------------
__device__ __forceinline__ float ex2f(float x) {
    float r;
    asm("ex2.approx.ftz.f32 %0, %1;" : "=f"(r) : "f"(x));
    return r;
}
__device__ __forceinline__ uint32_t h2ex2(uint32_t x) {
    uint32_t r;
    asm("ex2.approx.f16x2 %0, %1;" : "=r"(r) : "r"(x));
    return r;
}
__device__ __forceinline__ void mma_f16(float& d0, float& d1, float& d2, float& d3,
                                        uint32_t a0, uint32_t a1, uint32_t a2, uint32_t a3,
                                        uint32_t b0, uint32_t b1) {
    asm volatile(
        "mma.sync.aligned.m16n8k16.row.col.f32.f16.f16.f32 "
        "{%0,%1,%2,%3}, {%4,%5,%6,%7}, {%8,%9}, {%0,%1,%2,%3};\n"
        : "+f"(d0), "+f"(d1), "+f"(d2), "+f"(d3)
        : "r"(a0), "r"(a1), "r"(a2), "r"(a3), "r"(b0), "r"(b1));
}
__device__ __forceinline__ void ldsm_x4(uint32_t& r0, uint32_t& r1, uint32_t& r2, uint32_t& r3,
                                        uint32_t a) {
    asm volatile("ldmatrix.sync.aligned.m8n8.x4.shared.b16 {%0,%1,%2,%3}, [%4];\n"
                 : "=r"(r0), "=r"(r1), "=r"(r2), "=r"(r3) : "r"(a));
}
__device__ __forceinline__ uint32_t smem_u32(const void* p) {
    return (uint32_t)__cvta_generic_to_shared(p);
}
__device__ __forceinline__ void cpa16(uint32_t s, const void* g) {
    asm volatile("cp.async.ca.shared.global [%0], [%1], 16;\n" :: "r"(s), "l"(g));
}
__device__ __forceinline__ void cpa_commit() { asm volatile("cp.async.commit_group;\n"); }
template <int N>
__device__ __forceinline__ void cpa_wait() { asm volatile("cp.async.wait_group %0;\n" :: "n"(N)); }

// ---------------------------------------------------------------------------
// Prep (merged): blk [0,512): blob f32->f16 + 2x2 maxpool.
//                blk [512,608): weights f32 [k][n] -> f16 [mode][n][k].
// ---------------------------------------------------------------------------
__global__ __launch_bounds__(256)
void prep_all(const float* __restrict__ blob,
              const float* __restrict__ wq, const float* __restrict__ wk,
              const float* __restrict__ wv)
{
    if (blockIdx.x < 512) {
        const int idx = blockIdx.x * 256 + threadIdx.x;    // 131072 total
        const int pp  = idx >> 5;
        const int c8  = (idx & 31) << 3;
        const int b  = pp >> 10, l = pp & 1023, h2 = l >> 5, w2 = l & 31;
        const int pix = (b * HH + 2 * h2) * WW + 2 * w2;
        const float* p = blob + (size_t)pix * DD + c8;

        float mx[8];
#pragma unroll
        for (int j = 0; j < 8; j++) mx[j] = -INFINITY;
        const int offs[4] = {0, DD, WW * DD, WW * DD + DD};
#pragma unroll
        for (int q = 0; q < 4; q++) {
            float4 v0 = *(const float4*)(p + offs[q]);
            float4 v1 = *(const float4*)(p + offs[q] + 4);
            float vv[8] = {v0.x, v0.y, v0.z, v0.w, v1.x, v1.y, v1.z, v1.w};
            __half hh[8];
#pragma unroll
            for (int j = 0; j < 8; j++) {
                hh[j] = __float2half_rn(vv[j]);
                mx[j] = fmaxf(mx[j], vv[j]);
            }
            const int pixq = pix + ((q >> 1) ? WW : 0) + (q & 1);
            *(uint4*)(g_a16 + (size_t)pixq * DD + c8) = *(uint4*)hh;
        }
        __half hm[8];
#pragma unroll
        for (int j = 0; j < 8; j++) hm[j] = __float2half_rn(mx[j]);
        *(uint4*)(g_p16 + (size_t)pp * DD + c8) = *(uint4*)hm;
    } else {
        const int idx = (blockIdx.x - 512) * 256 + threadIdx.x;   // 24576 total
        const int m   = idx >> 13;
        const int r   = idx & 8191;
        const int n   = r >> 5;
        const int k0  = (r & 31) << 3;
        const float* Wm = (m == 0) ? wq : (m == 1) ? wk : wv;
        __half tmp[8];
#pragma unroll
        for (int j = 0; j < 8; j++)
            tmp[j] = __float2half_rn(Wm[(size_t)(k0 + j) * DD + n]);
        *(uint4*)(g_w16 + ((size_t)m * DD + n) * DD + k0) = *(uint4*)tmp;
    }
}

// ---------------------------------------------------------------------------
// f16 tensor-core projections: 576 blocks (unchanged).
// ---------------------------------------------------------------------------
__global__ __launch_bounds__(256, 2)
void proj_gemm(const float* __restrict__ bq, const float* __restrict__ bk,
               const float* __restrict__ bv)
{
    __shared__ __half As[2][128][40];
    __shared__ __half Ws[2][128][40];

    const int tid  = threadIdx.x;
    const int w    = tid >> 5;
    const int lane = tid & 31;
    const int g    = lane >> 2;
    const int tig  = lane & 3;
    const int rsel = lane & 7;
    const int quad = lane >> 3;
    const int mw   = w & 3;
    const int nw   = w >> 2;

    const int blk = blockIdx.x;
    int mode, mt, n0;
    if (blk < 64)       { mode = 0; mt = blk >> 1;          n0 = (blk & 1) << 7; }
    else if (blk < 320) { mode = 1; mt = (blk - 64) >> 1;   n0 = (blk & 1) << 7; }
    else                { mode = 2; mt = (blk - 320) >> 1;  n0 = (blk & 1) << 7; }
    const int m0 = mt << 7;

    const __half* Aptr = (mode == 0) ? g_p16 : g_a16;
    const __half* Wptr = g_w16 + (size_t)mode * DD * DD;
    const float*  bias = (mode == 0) ? bq : (mode == 1) ? bk : bv;

    auto stage = [&](int k0, int buf) {
#pragma unroll
        for (int t = 0; t < 2; t++) {
            const int i   = tid + 256 * t;
            const int row = i >> 2;
            const int c   = i & 3;
            cpa16(smem_u32(&As[buf][row][c * 8]), Aptr + (size_t)(m0 + row) * DD + k0 + c * 8);
            cpa16(smem_u32(&Ws[buf][row][c * 8]), Wptr + (size_t)(n0 + row) * DD + k0 + c * 8);
        }
    };

    float acc[2][8][4];
#pragma unroll
    for (int t = 0; t < 2; t++)
#pragma unroll
        for (int nt = 0; nt < 8; nt++)
#pragma unroll
            for (int j = 0; j < 4; j++) acc[t][nt][j] = 0.0f;

    stage(0, 0);
    cpa_commit();

    for (int ks = 0; ks < 8; ks++) {
        const int buf = ks & 1;
        if (ks + 1 < 8) {
            stage((ks + 1) * 32, buf ^ 1);
            cpa_commit();
            cpa_wait<1>();
        } else {
            cpa_wait<0>();
        }
        __syncthreads();

#pragma unroll
        for (int kc = 0; kc < 2; kc++) {
            uint32_t af[2][4];
#pragma unroll
            for (int t = 0; t < 2; t++) {
                const uint32_t addr = smem_u32(
                    &As[buf][mw * 32 + t * 16 + rsel + ((quad & 1) << 3)]
                            [kc * 16 + ((quad >> 1) << 3)]);
                ldsm_x4(af[t][0], af[t][1], af[t][2], af[t][3], addr);
            }
#pragma unroll
            for (int p = 0; p < 4; p++) {
                uint32_t b0, b1, b2, b3;
                const uint32_t addr = smem_u32(
                    &Ws[buf][nw * 64 + p * 16 + rsel + ((quad >> 1) << 3)]
                            [kc * 16 + ((quad & 1) << 3)]);
                ldsm_x4(b0, b1, b2, b3, addr);
#pragma unroll
                for (int t = 0; t < 2; t++) {
                    mma_f16(acc[t][2 * p][0], acc[t][2 * p][1], acc[t][2 * p][2], acc[t][2 * p][3],
                            af[t][0], af[t][1], af[t][2], af[t][3], b0, b1);
                    mma_f16(acc[t][2 * p + 1][0], acc[t][2 * p + 1][1], acc[t][2 * p + 1][2], acc[t][2 * p + 1][3],
                            af[t][0], af[t][1], af[t][2], af[t][3], b2, b3);
                }
            }
        }
        __syncthreads();
    }

    const float QSCL = 0.17677669529663687f * 1.4426950408889634f;
#pragma unroll
    for (int t = 0; t < 2; t++) {
#pragma unroll
        for (int nt = 0; nt < 8; nt++) {
#pragma unroll
            for (int half = 0; half < 2; half++) {
                const int r = m0 + mw * 32 + t * 16 + g + half * 8;
#pragma unroll
                for (int j = 0; j < 2; j++) {
                    const int c = n0 + nw * 64 + nt * 8 + 2 * tig + j;
                    float val   = acc[t][nt][half * 2 + j] + __ldg(bias + c);
                    const int n = c >> 5;
                    const int d = c & 31;
                    if (mode == 0) {
                        val *= QSCL;
                        const int b = r >> 10, p2 = r & 1023;
                        g_q[(((b * NH + n) * P2) + p2) * DK + d] = __float2half_rn(val);
                    } else if (mode == 1) {
                        const int b = r >> 12, ii = r & 4095;
                        g_k[(((b * NH + n) * HW) + ii) * DK + d] = __float2half_rn(val);
                    } else {
                        val = val / (1.0f + __expf(-val));
                        const int b = r >> 12, ii = r & 4095;
                        g_v[(((size_t)(b * NH + n) * DV) + d) * HW + ii] = __float2half_rn(val);
                    }
                }
            }
        }
    }
}

// ---------------------------------------------------------------------------
// Split-K fp16 flash attention (SPLIT=4 -> 1024 blocks, 16 tiles each).
// Block: 8 warps / 256 thr / 128 queries; 1024 keys; 64-key tiles.
// 3-stage cp.async pipeline (one barrier per tile); warp-uniform lazy max;
// row-sum l via ones-fragment MMA.
// ---------------------------------------------------------------------------
__global__ __launch_bounds__(256)
void attn_tc_kernel()
{
    __shared__ __half Qs[128][40];
    __shared__ __half Ks[3][64][40];
    __shared__ __half VsT[3][32][72];

    const int tid  = threadIdx.x;
    const int w    = tid >> 5;            // 0..7
    const int lane = tid & 31;
    const int g    = lane >> 2;
    const int tig  = lane & 3;
    const int rsel = lane & 7;
    const int quad = lane >> 3;

    const int qt = blockIdx.x;            // 0..7 (128 queries each)
    const int n  = blockIdx.y;
    const int z  = blockIdx.z;            // 0..15
    const int b  = z >> 2;
    const int s  = z & 3;                 // key split 0..3
    const int bn = b * NH + n;

    const __half* qglob = g_q + (size_t)(bn * P2 + qt * 128) * DK;
    const __half* kglob = g_k + ((size_t)bn * HW + s * KSPS) * DK;
    const __half* vglob = g_v + (size_t)bn * DV * HW + s * KSPS;

    // stage Q once: 128 rows x 64B = 512 x 16B
#pragma unroll
    for (int t = 0; t < 2; t++) {
        const int i   = tid + 256 * t;
        const int row = i >> 2;
        const int c   = i & 3;
        *(float4*)&Qs[row][c * 8] = *(const float4*)(qglob + row * DK + c * 8);
    }

    auto stage = [&](int j0, int buf) {
        {   // K: 64 rows x 64B = 256 chunks
            const int row = tid >> 2;
            const int c   = tid & 3;
            cpa16(smem_u32(&Ks[buf][row][c * 8]), kglob + (size_t)(j0 + row) * DK + c * 8);
        }
        {   // V^T: 32 rows x 128B = 256 chunks
            const int row = tid >> 3;
            const int c   = tid & 7;
            cpa16(smem_u32(&VsT[buf][row][c * 8]), vglob + (size_t)row * HW + j0 + c * 8);
        }
    };

    const int NT = KSPS / 64;             // 16
    stage(0, 0);   cpa_commit();
    stage(64, 1);  cpa_commit();
    __syncthreads();                      // Qs visible

    uint32_t Qf[2][4];
    const int r0 = w * 16 + g;
#pragma unroll
    for (int kc = 0; kc < 2; kc++) {
        Qf[kc][0] = *(const uint32_t*)&Qs[r0    ][kc * 16 + 2 * tig    ];
        Qf[kc][1] = *(const uint32_t*)&Qs[r0 + 8][kc * 16 + 2 * tig    ];
        Qf[kc][2] = *(const uint32_t*)&Qs[r0    ][kc * 16 + 2 * tig + 8];
        Qf[kc][3] = *(const uint32_t*)&Qs[r0 + 8][kc * 16 + 2 * tig + 8];
    }

    float m = -INFINITY;                  // warp-uniform running max (log2 domain)
    float lacc[4] = {0.0f, 0.0f, 0.0f, 0.0f};
    float oacc[4][4];
#pragma unroll
    for (int i = 0; i < 4; i++)
#pragma unroll
        for (int j = 0; j < 4; j++) oacc[i][j] = 0.0f;

    for (int it = 0; it < NT; it++) {
        const int buf = it % 3;
        if (it == NT - 1) cpa_wait<0>(); else cpa_wait<1>();
        __syncthreads();                  // one barrier per tile

        // ---- S = Q K^T ----
        float sacc[8][4];
#pragma unroll
        for (int nt = 0; nt < 8; nt++)
#pragma unroll
            for (int j = 0; j < 4; j++) sacc[nt][j] = 0.0f;

#pragma unroll
        for (int kc = 0; kc < 2; kc++) {
#pragma unroll
            for (int p = 0; p < 4; p++) {
                uint32_t b0, b1, b2, b3;
                const uint32_t addr = smem_u32(
                    &Ks[buf][p * 16 + rsel + ((quad >> 1) << 3)]
                            [kc * 16 + ((quad & 1) << 3)]);
                ldsm_x4(b0, b1, b2, b3, addr);
                mma_f16(sacc[2 * p][0], sacc[2 * p][1], sacc[2 * p][2], sacc[2 * p][3],
                        Qf[kc][0], Qf[kc][1], Qf[kc][2], Qf[kc][3], b0, b1);
                mma_f16(sacc[2 * p + 1][0], sacc[2 * p + 1][1], sacc[2 * p + 1][2], sacc[2 * p + 1][3],
                        Qf[kc][0], Qf[kc][1], Qf[kc][2], Qf[kc][3], b2, b3);
            }
        }

        // ---- warp-uniform lazy max ----
        float mx = -INFINITY;
#pragma unroll
        for (int nt = 0; nt < 8; nt++) {
            mx = fmaxf(mx, fmaxf(fmaxf(sacc[nt][0], sacc[nt][1]),
                                 fmaxf(sacc[nt][2], sacc[nt][3])));
        }
#pragma unroll
        for (int d = 16; d >= 1; d >>= 1)
            mx = fmaxf(mx, __shfl_xor_sync(0xffffffffu, mx, d));

        if (mx > m) {                     // warp-uniform branch; rare after warmup
            const float sc = ex2f(m - mx);   // 0 on first tile
            m = mx;
#pragma unroll
            for (int nt = 0; nt < 4; nt++) {
                oacc[nt][0] *= sc; oacc[nt][1] *= sc;
                oacc[nt][2] *= sc; oacc[nt][3] *= sc;
            }
            lacc[0] *= sc; lacc[1] *= sc; lacc[2] *= sc; lacc[3] *= sc;
        }

        // ---- P = 2^(S - m) in f16 ----
        uint32_t hlo[8], hhi[8];
#pragma unroll
        for (int nt = 0; nt < 8; nt++) {
            __half2 d0 = __floats2half2_rn(sacc[nt][0] - m, sacc[nt][1] - m);
            __half2 d1 = __floats2half2_rn(sacc[nt][2] - m, sacc[nt][3] - m);
            hlo[nt] = h2ex2(*(uint32_t*)&d0);
            hhi[nt] = h2ex2(*(uint32_t*)&d1);
        }

        // ---- O += P V ; l += P @ 1 ----
#pragma unroll
        for (int kc = 0; kc < 4; kc++) {
            const uint32_t a0 = hlo[2 * kc];
            const uint32_t a1 = hhi[2 * kc];
            const uint32_t a2 = hlo[2 * kc + 1];
            const uint32_t a3 = hhi[2 * kc + 1];
            mma_f16(lacc[0], lacc[1], lacc[2], lacc[3],
                    a0, a1, a2, a3, ONES_F16X2, ONES_F16X2);
#pragma unroll
            for (int p = 0; p < 2; p++) {
                uint32_t b0, b1, b2, b3;
                const uint32_t addr = smem_u32(
                    &VsT[buf][p * 16 + rsel + ((quad >> 1) << 3)]
                             [kc * 16 + ((quad & 1) << 3)]);
                ldsm_x4(b0, b1, b2, b3, addr);
                mma_f16(oacc[2 * p][0], oacc[2 * p][1], oacc[2 * p][2], oacc[2 * p][3],
                        a0, a1, a2, a3, b0, b1);
                mma_f16(oacc[2 * p + 1][0], oacc[2 * p + 1][1], oacc[2 * p + 1][2], oacc[2 * p + 1][3],
                        a0, a1, a2, a3, b2, b3);
            }
        }

        // stage tile it+2 into buffer (it+2)%3
        if (it + 2 < NT) {
            stage((it + 2) * 64, (it + 2) % 3);
            cpa_commit();
        }
    }

    // ---- write partials (unnormalized) ----
    const int q0   = qt * 128 + w * 16 + g;
    const int row0 = bn * P2 + q0;
    const int row1 = row0 + 8;
    if (tig == 0) {
        g_pm[s][row0] = m;   g_pl[s][row0] = lacc[0];
        g_pm[s][row1] = m;   g_pl[s][row1] = lacc[2];
    }
    float* po0 = &g_po[s][(size_t)row0 * DV];
    float* po1 = &g_po[s][(size_t)row1 * DV];
#pragma unroll
    for (int nt = 0; nt < 4; nt++) {
        *(float2*)(po0 + nt * 8 + 2 * tig) = make_float2(oacc[nt][0], oacc[nt][1]);
        *(float2*)(po1 + nt * 8 + 2 * tig) = make_float2(oacc[nt][2], oacc[nt][3]);
    }
}

// ---------------------------------------------------------------------------
// Combine the four key-splits and normalize (8 elems/thread, float4).
// ---------------------------------------------------------------------------
__global__ __launch_bounds__(256)
void combine_kernel(float* __restrict__ out)
{
    const int idx = blockIdx.x * 256 + threadIdx.x;    // 131072 total
    const int row = idx >> 2;                          // bn*P2 + p
    const int d0  = (idx & 3) << 3;

    float pm[SPLIT];
#pragma unroll
    for (int s = 0; s < SPLIT; s++) pm[s] = g_pm[s][row];
    float M = pm[0];
#pragma unroll
    for (int s = 1; s < SPLIT; s++) M = fmaxf(M, pm[s]);

    float wgt[SPLIT];
    float den = 0.0f;
#pragma unroll
    for (int s = 0; s < SPLIT; s++) {
        wgt[s] = ex2f(pm[s] - M);
        den += g_pl[s][row] * wgt[s];
    }
    const float inv = 1.0f / den;
#pragma unroll
    for (int s = 0; s < SPLIT; s++) wgt[s] *= inv;

    const int b = row >> 13;
    const int n = (row >> 10) & 7;
    const int p = row & 1023;
    float4* o = (float4*)(out + ((size_t)(b * P2 + p) * 256) + n * DV + d0);

#pragma unroll
    for (int t = 0; t < 2; t++) {
        float4 r = make_float4(0.0f, 0.0f, 0.0f, 0.0f);
#pragma unroll
        for (int s = 0; s < SPLIT; s++) {
            float4 x = *(const float4*)&g_po[s][(size_t)row * DV + d0 + 4 * t];
            r.x += x.x * wgt[s];
            r.y += x.y * wgt[s];
            r.z += x.z * wgt[s];
            r.w += x.w * wgt[s];
        }
        o[t] = r;
    }
}

// ---------------------------------------------------------------------------
extern "C" void kernel_launch(void* const* d_in, const int* in_sizes, int n_in,
                              void* d_out, int out_size)
{
    const float* blob = (const float*)d_in[0];
    const float* wq   = (const float*)d_in[1];
    const float* bq   = (const float*)d_in[2];
    const float* wk   = (const float*)d_in[3];
    const float* bk   = (const float*)d_in[4];
    const float* wv   = (const float*)d_in[5];
    const float* bv   = (const float*)d_in[6];
    float* out        = (float*)d_out;

    prep_all<<<608, 256>>>(blob, wq, wk, wv);
    proj_gemm<<<576, 256>>>(bq, bk, bv);
    attn_tc_kernel<<<dim3(8, NH, BB * SPLIT), 256>>>();
    combine_kernel<<<512, 256>>>(out);
}

// round 10
// speedup vs baseline: 8.3447x; 1.0012x over previous
#include <cuda_runtime.h>
#include <cuda_fp16.h>
#include <math.h>
#include <stdint.h>

// Problem constants
#define BB 4
#define HH 64
#define WW 64
#define DD 256
#define NH 8
#define DK 32
#define DV 32
#define HW 4096
#define P2 1024
#define SPLIT 4
#define KSPS 1024        // keys per split

// Scratch
__device__ __half g_a16[BB * HW * DD];           //  8 MB blob f16
__device__ __half g_p16[BB * P2 * DD];           //  2 MB pooled blob f16
__device__ __half g_w16[3 * DD * DD];            // weights f16 [mode][n][k]
__device__ __half g_q[BB * NH * P2 * DK];        //  2 MB [bn][p][k] (pre-scaled 1/sqrt(K)*log2e)
__device__ __half g_k[BB * NH * HW * DK];        //  8 MB [bn][i][k]
__device__ __half g_v[BB * NH * DV * HW];        //  8 MB [bn][d][i] TRANSPOSED
__device__ float  g_po[SPLIT][BB * NH * P2 * DV];// 16 MB unnormalized partial O
__device__ float  g_pm[SPLIT][BB * NH * P2];     // partial max (log2 domain)
__device__ float  g_pl[SPLIT][BB * NH * P2];     // partial sum

#define ONES_F16X2 0x3C003C00u

// ---------------------------------------------------------------------------
__device__ __forceinline__ float ex2f(float x) {
    float r;
    asm("ex2.approx.ftz.f32 %0, %1;" : "=f"(r) : "f"(x));
    return r;
}
__device__ __forceinline__ uint32_t h2ex2(uint32_t x) {
    uint32_t r;
    asm("ex2.approx.f16x2 %0, %1;" : "=r"(r) : "r"(x));
    return r;
}
__device__ __forceinline__ void mma_f16(float& d0, float& d1, float& d2, float& d3,
                                        uint32_t a0, uint32_t a1, uint32_t a2, uint32_t a3,
                                        uint32_t b0, uint32_t b1) {
    asm volatile(
        "mma.sync.aligned.m16n8k16.row.col.f32.f16.f16.f32 "
        "{%0,%1,%2,%3}, {%4,%5,%6,%7}, {%8,%9}, {%0,%1,%2,%3};\n"
        : "+f"(d0), "+f"(d1), "+f"(d2), "+f"(d3)
        : "r"(a0), "r"(a1), "r"(a2), "r"(a3), "r"(b0), "r"(b1));
}
__device__ __forceinline__ void ldsm_x4(uint32_t& r0, uint32_t& r1, uint32_t& r2, uint32_t& r3,
                                        uint32_t a) {
    asm volatile("ldmatrix.sync.aligned.m8n8.x4.shared.b16 {%0,%1,%2,%3}, [%4];\n"
                 : "=r"(r0), "=r"(r1), "=r"(r2), "=r"(r3) : "r"(a));
}
__device__ __forceinline__ uint32_t smem_u32(const void* p) {
    return (uint32_t)__cvta_generic_to_shared(p);
}
__device__ __forceinline__ void cpa16(uint32_t s, const void* g) {
    asm volatile("cp.async.ca.shared.global [%0], [%1], 16;\n" :: "r"(s), "l"(g));
}
__device__ __forceinline__ void cpa_commit() { asm volatile("cp.async.commit_group;\n"); }
template <int N>
__device__ __forceinline__ void cpa_wait() { asm volatile("cp.async.wait_group %0;\n" :: "n"(N)); }

// ---------------------------------------------------------------------------
// Prep (merged): blk [0,512): blob f32->f16 + 2x2 maxpool.
//                blk [512,608): weights f32 [k][n] -> f16 [mode][n][k].
// ---------------------------------------------------------------------------
__global__ __launch_bounds__(256)
void prep_all(const float* __restrict__ blob,
              const float* __restrict__ wq, const float* __restrict__ wk,
              const float* __restrict__ wv)
{
    if (blockIdx.x < 512) {
        const int idx = blockIdx.x * 256 + threadIdx.x;    // 131072 total
        const int pp  = idx >> 5;
        const int c8  = (idx & 31) << 3;
        const int b  = pp >> 10, l = pp & 1023, h2 = l >> 5, w2 = l & 31;
        const int pix = (b * HH + 2 * h2) * WW + 2 * w2;
        const float* p = blob + (size_t)pix * DD + c8;

        float mx[8];
#pragma unroll
        for (int j = 0; j < 8; j++) mx[j] = -INFINITY;
        const int offs[4] = {0, DD, WW * DD, WW * DD + DD};
#pragma unroll
        for (int q = 0; q < 4; q++) {
            float4 v0 = *(const float4*)(p + offs[q]);
            float4 v1 = *(const float4*)(p + offs[q] + 4);
            float vv[8] = {v0.x, v0.y, v0.z, v0.w, v1.x, v1.y, v1.z, v1.w};
            __half hh[8];
#pragma unroll
            for (int j = 0; j < 8; j++) {
                hh[j] = __float2half_rn(vv[j]);
                mx[j] = fmaxf(mx[j], vv[j]);
            }
            const int pixq = pix + ((q >> 1) ? WW : 0) + (q & 1);
            *(uint4*)(g_a16 + (size_t)pixq * DD + c8) = *(uint4*)hh;
        }
        __half hm[8];
#pragma unroll
        for (int j = 0; j < 8; j++) hm[j] = __float2half_rn(mx[j]);
        *(uint4*)(g_p16 + (size_t)pp * DD + c8) = *(uint4*)hm;
    } else {
        const int idx = (blockIdx.x - 512) * 256 + threadIdx.x;   // 24576 total
        const int m   = idx >> 13;
        const int r   = idx & 8191;
        const int n   = r >> 5;
        const int k0  = (r & 31) << 3;
        const float* Wm = (m == 0) ? wq : (m == 1) ? wk : wv;
        __half tmp[8];
#pragma unroll
        for (int j = 0; j < 8; j++)
            tmp[j] = __float2half_rn(Wm[(size_t)(k0 + j) * DD + n]);
        *(uint4*)(g_w16 + ((size_t)m * DD + n) * DD + k0) = *(uint4*)tmp;
    }
}

// ---------------------------------------------------------------------------
// f16 tensor-core projections: 576 blocks (unchanged).
// ---------------------------------------------------------------------------
__global__ __launch_bounds__(256, 2)
void proj_gemm(const float* __restrict__ bq, const float* __restrict__ bk,
               const float* __restrict__ bv)
{
    __shared__ __half As[2][128][40];
    __shared__ __half Ws[2][128][40];

    const int tid  = threadIdx.x;
    const int w    = tid >> 5;
    const int lane = tid & 31;
    const int g    = lane >> 2;
    const int tig  = lane & 3;
    const int rsel = lane & 7;
    const int quad = lane >> 3;
    const int mw   = w & 3;
    const int nw   = w >> 2;

    const int blk = blockIdx.x;
    int mode, mt, n0;
    if (blk < 64)       { mode = 0; mt = blk >> 1;          n0 = (blk & 1) << 7; }
    else if (blk < 320) { mode = 1; mt = (blk - 64) >> 1;   n0 = (blk & 1) << 7; }
    else                { mode = 2; mt = (blk - 320) >> 1;  n0 = (blk & 1) << 7; }
    const int m0 = mt << 7;

    const __half* Aptr = (mode == 0) ? g_p16 : g_a16;
    const __half* Wptr = g_w16 + (size_t)mode * DD * DD;
    const float*  bias = (mode == 0) ? bq : (mode == 1) ? bk : bv;

    auto stage = [&](int k0, int buf) {
#pragma unroll
        for (int t = 0; t < 2; t++) {
            const int i   = tid + 256 * t;
            const int row = i >> 2;
            const int c   = i & 3;
            cpa16(smem_u32(&As[buf][row][c * 8]), Aptr + (size_t)(m0 + row) * DD + k0 + c * 8);
            cpa16(smem_u32(&Ws[buf][row][c * 8]), Wptr + (size_t)(n0 + row) * DD + k0 + c * 8);
        }
    };

    float acc[2][8][4];
#pragma unroll
    for (int t = 0; t < 2; t++)
#pragma unroll
        for (int nt = 0; nt < 8; nt++)
#pragma unroll
            for (int j = 0; j < 4; j++) acc[t][nt][j] = 0.0f;

    stage(0, 0);
    cpa_commit();

    for (int ks = 0; ks < 8; ks++) {
        const int buf = ks & 1;
        if (ks + 1 < 8) {
            stage((ks + 1) * 32, buf ^ 1);
            cpa_commit();
            cpa_wait<1>();
        } else {
            cpa_wait<0>();
        }
        __syncthreads();

#pragma unroll
        for (int kc = 0; kc < 2; kc++) {
            uint32_t af[2][4];
#pragma unroll
            for (int t = 0; t < 2; t++) {
                const uint32_t addr = smem_u32(
                    &As[buf][mw * 32 + t * 16 + rsel + ((quad & 1) << 3)]
                            [kc * 16 + ((quad >> 1) << 3)]);
                ldsm_x4(af[t][0], af[t][1], af[t][2], af[t][3], addr);
            }
#pragma unroll
            for (int p = 0; p < 4; p++) {
                uint32_t b0, b1, b2, b3;
                const uint32_t addr = smem_u32(
                    &Ws[buf][nw * 64 + p * 16 + rsel + ((quad >> 1) << 3)]
                            [kc * 16 + ((quad & 1) << 3)]);
                ldsm_x4(b0, b1, b2, b3, addr);
#pragma unroll
                for (int t = 0; t < 2; t++) {
                    mma_f16(acc[t][2 * p][0], acc[t][2 * p][1], acc[t][2 * p][2], acc[t][2 * p][3],
                            af[t][0], af[t][1], af[t][2], af[t][3], b0, b1);
                    mma_f16(acc[t][2 * p + 1][0], acc[t][2 * p + 1][1], acc[t][2 * p + 1][2], acc[t][2 * p + 1][3],
                            af[t][0], af[t][1], af[t][2], af[t][3], b2, b3);
                }
            }
        }
        __syncthreads();
    }

    const float QSCL = 0.17677669529663687f * 1.4426950408889634f;
#pragma unroll
    for (int t = 0; t < 2; t++) {
#pragma unroll
        for (int nt = 0; nt < 8; nt++) {
#pragma unroll
            for (int half = 0; half < 2; half++) {
                const int r = m0 + mw * 32 + t * 16 + g + half * 8;
#pragma unroll
                for (int j = 0; j < 2; j++) {
                    const int c = n0 + nw * 64 + nt * 8 + 2 * tig + j;
                    float val   = acc[t][nt][half * 2 + j] + __ldg(bias + c);
                    const int n = c >> 5;
                    const int d = c & 31;
                    if (mode == 0) {
                        val *= QSCL;
                        const int b = r >> 10, p2 = r & 1023;
                        g_q[(((b * NH + n) * P2) + p2) * DK + d] = __float2half_rn(val);
                    } else if (mode == 1) {
                        const int b = r >> 12, ii = r & 4095;
                        g_k[(((b * NH + n) * HW) + ii) * DK + d] = __float2half_rn(val);
                    } else {
                        val = val / (1.0f + __expf(-val));
                        const int b = r >> 12, ii = r & 4095;
                        g_v[(((size_t)(b * NH + n) * DV) + d) * HW + ii] = __float2half_rn(val);
                    }
                }
            }
        }
    }
}

// ---------------------------------------------------------------------------
// Split-K fp16 flash attention (SPLIT=4 -> 1024 blocks, 16 tiles each).
// Block: 8 warps / 256 thr / 128 queries; 1024 keys; 64-key tiles.
// 3-stage cp.async pipeline (one barrier per tile); warp-uniform lazy max;
// row-sum l via ones-fragment MMA.
// ---------------------------------------------------------------------------
__global__ __launch_bounds__(256)
void attn_tc_kernel()
{
    __shared__ __half Qs[128][40];
    __shared__ __half Ks[3][64][40];
    __shared__ __half VsT[3][32][72];

    const int tid  = threadIdx.x;
    const int w    = tid >> 5;            // 0..7
    const int lane = tid & 31;
    const int g    = lane >> 2;
    const int tig  = lane & 3;
    const int rsel = lane & 7;
    const int quad = lane >> 3;

    const int qt = blockIdx.x;            // 0..7 (128 queries each)
    const int n  = blockIdx.y;
    const int z  = blockIdx.z;            // 0..15
    const int b  = z >> 2;
    const int s  = z & 3;                 // key split 0..3
    const int bn = b * NH + n;

    const __half* qglob = g_q + (size_t)(bn * P2 + qt * 128) * DK;
    const __half* kglob = g_k + ((size_t)bn * HW + s * KSPS) * DK;
    const __half* vglob = g_v + (size_t)bn * DV * HW + s * KSPS;

    // stage Q once: 128 rows x 64B = 512 x 16B
#pragma unroll
    for (int t = 0; t < 2; t++) {
        const int i   = tid + 256 * t;
        const int row = i >> 2;
        const int c   = i & 3;
        *(float4*)&Qs[row][c * 8] = *(const float4*)(qglob + row * DK + c * 8);
    }

    auto stage = [&](int j0, int buf) {
        {   // K: 64 rows x 64B = 256 chunks
            const int row = tid >> 2;
            const int c   = tid & 3;
            cpa16(smem_u32(&Ks[buf][row][c * 8]), kglob + (size_t)(j0 + row) * DK + c * 8);
        }
        {   // V^T: 32 rows x 128B = 256 chunks
            const int row = tid >> 3;
            const int c   = tid & 7;
            cpa16(smem_u32(&VsT[buf][row][c * 8]), vglob + (size_t)row * HW + j0 + c * 8);
        }
    };

    const int NT = KSPS / 64;             // 16
    stage(0, 0);   cpa_commit();
    stage(64, 1);  cpa_commit();
    __syncthreads();                      // Qs visible

    uint32_t Qf[2][4];
    const int r0 = w * 16 + g;
#pragma unroll
    for (int kc = 0; kc < 2; kc++) {
        Qf[kc][0] = *(const uint32_t*)&Qs[r0    ][kc * 16 + 2 * tig    ];
        Qf[kc][1] = *(const uint32_t*)&Qs[r0 + 8][kc * 16 + 2 * tig    ];
        Qf[kc][2] = *(const uint32_t*)&Qs[r0    ][kc * 16 + 2 * tig + 8];
        Qf[kc][3] = *(const uint32_t*)&Qs[r0 + 8][kc * 16 + 2 * tig + 8];
    }

    float m = -INFINITY;                  // warp-uniform running max (log2 domain)
    float lacc[4] = {0.0f, 0.0f, 0.0f, 0.0f};
    float oacc[4][4];
#pragma unroll
    for (int i = 0; i < 4; i++)
#pragma unroll
        for (int j = 0; j < 4; j++) oacc[i][j] = 0.0f;

    for (int it = 0; it < NT; it++) {
        const int buf = it % 3;
        if (it == NT - 1) cpa_wait<0>(); else cpa_wait<1>();
        __syncthreads();                  // one barrier per tile

        // ---- S = Q K^T ----
        float sacc[8][4];
#pragma unroll
        for (int nt = 0; nt < 8; nt++)
#pragma unroll
            for (int j = 0; j < 4; j++) sacc[nt][j] = 0.0f;

#pragma unroll
        for (int kc = 0; kc < 2; kc++) {
#pragma unroll
            for (int p = 0; p < 4; p++) {
                uint32_t b0, b1, b2, b3;
                const uint32_t addr = smem_u32(
                    &Ks[buf][p * 16 + rsel + ((quad >> 1) << 3)]
                            [kc * 16 + ((quad & 1) << 3)]);
                ldsm_x4(b0, b1, b2, b3, addr);
                mma_f16(sacc[2 * p][0], sacc[2 * p][1], sacc[2 * p][2], sacc[2 * p][3],
                        Qf[kc][0], Qf[kc][1], Qf[kc][2], Qf[kc][3], b0, b1);
                mma_f16(sacc[2 * p + 1][0], sacc[2 * p + 1][1], sacc[2 * p + 1][2], sacc[2 * p + 1][3],
                        Qf[kc][0], Qf[kc][1], Qf[kc][2], Qf[kc][3], b2, b3);
            }
        }

        // ---- warp-uniform lazy max ----
        float mx = -INFINITY;
#pragma unroll
        for (int nt = 0; nt < 8; nt++) {
            mx = fmaxf(mx, fmaxf(fmaxf(sacc[nt][0], sacc[nt][1]),
                                 fmaxf(sacc[nt][2], sacc[nt][3])));
        }
#pragma unroll
        for (int d = 16; d >= 1; d >>= 1)
            mx = fmaxf(mx, __shfl_xor_sync(0xffffffffu, mx, d));

        if (mx > m) {                     // warp-uniform branch; rare after warmup
            const float sc = ex2f(m - mx);   // 0 on first tile
            m = mx;
#pragma unroll
            for (int nt = 0; nt < 4; nt++) {
                oacc[nt][0] *= sc; oacc[nt][1] *= sc;
                oacc[nt][2] *= sc; oacc[nt][3] *= sc;
            }
            lacc[0] *= sc; lacc[1] *= sc; lacc[2] *= sc; lacc[3] *= sc;
        }

        // ---- P = 2^(S - m) in f16 ----
        uint32_t hlo[8], hhi[8];
#pragma unroll
        for (int nt = 0; nt < 8; nt++) {
            __half2 d0 = __floats2half2_rn(sacc[nt][0] - m, sacc[nt][1] - m);
            __half2 d1 = __floats2half2_rn(sacc[nt][2] - m, sacc[nt][3] - m);
            hlo[nt] = h2ex2(*(uint32_t*)&d0);
            hhi[nt] = h2ex2(*(uint32_t*)&d1);
        }

        // ---- O += P V ; l += P @ 1 ----
#pragma unroll
        for (int kc = 0; kc < 4; kc++) {
            const uint32_t a0 = hlo[2 * kc];
            const uint32_t a1 = hhi[2 * kc];
            const uint32_t a2 = hlo[2 * kc + 1];
            const uint32_t a3 = hhi[2 * kc + 1];
            mma_f16(lacc[0], lacc[1], lacc[2], lacc[3],
                    a0, a1, a2, a3, ONES_F16X2, ONES_F16X2);
#pragma unroll
            for (int p = 0; p < 2; p++) {
                uint32_t b0, b1, b2, b3;
                const uint32_t addr = smem_u32(
                    &VsT[buf][p * 16 + rsel + ((quad >> 1) << 3)]
                             [kc * 16 + ((quad & 1) << 3)]);
                ldsm_x4(b0, b1, b2, b3, addr);
                mma_f16(oacc[2 * p][0], oacc[2 * p][1], oacc[2 * p][2], oacc[2 * p][3],
                        a0, a1, a2, a3, b0, b1);
                mma_f16(oacc[2 * p + 1][0], oacc[2 * p + 1][1], oacc[2 * p + 1][2], oacc[2 * p + 1][3],
                        a0, a1, a2, a3, b2, b3);
            }
        }

        // stage tile it+2 into buffer (it+2)%3
        if (it + 2 < NT) {
            stage((it + 2) * 64, (it + 2) % 3);
            cpa_commit();
        }
    }

    // ---- write partials (unnormalized) ----
    const int q0   = qt * 128 + w * 16 + g;
    const int row0 = bn * P2 + q0;
    const int row1 = row0 + 8;
    if (tig == 0) {
        g_pm[s][row0] = m;   g_pl[s][row0] = lacc[0];
        g_pm[s][row1] = m;   g_pl[s][row1] = lacc[2];
    }
    float* po0 = &g_po[s][(size_t)row0 * DV];
    float* po1 = &g_po[s][(size_t)row1 * DV];
#pragma unroll
    for (int nt = 0; nt < 4; nt++) {
        *(float2*)(po0 + nt * 8 + 2 * tig) = make_float2(oacc[nt][0], oacc[nt][1]);
        *(float2*)(po1 + nt * 8 + 2 * tig) = make_float2(oacc[nt][2], oacc[nt][3]);
    }
}

// ---------------------------------------------------------------------------
// Combine the four key-splits and normalize (8 elems/thread, float4).
// ---------------------------------------------------------------------------
__global__ __launch_bounds__(256)
void combine_kernel(float* __restrict__ out)
{
    const int idx = blockIdx.x * 256 + threadIdx.x;    // 131072 total
    const int row = idx >> 2;                          // bn*P2 + p
    const int d0  = (idx & 3) << 3;

    float pm[SPLIT];
#pragma unroll
    for (int s = 0; s < SPLIT; s++) pm[s] = g_pm[s][row];
    float M = pm[0];
#pragma unroll
    for (int s = 1; s < SPLIT; s++) M = fmaxf(M, pm[s]);

    float wgt[SPLIT];
    float den = 0.0f;
#pragma unroll
    for (int s = 0; s < SPLIT; s++) {
        wgt[s] = ex2f(pm[s] - M);
        den += g_pl[s][row] * wgt[s];
    }
    const float inv = 1.0f / den;
#pragma unroll
    for (int s = 0; s < SPLIT; s++) wgt[s] *= inv;

    const int b = row >> 13;
    const int n = (row >> 10) & 7;
    const int p = row & 1023;
    float4* o = (float4*)(out + ((size_t)(b * P2 + p) * 256) + n * DV + d0);

#pragma unroll
    for (int t = 0; t < 2; t++) {
        float4 r = make_float4(0.0f, 0.0f, 0.0f, 0.0f);
#pragma unroll
        for (int s = 0; s < SPLIT; s++) {
            float4 x = *(const float4*)&g_po[s][(size_t)row * DV + d0 + 4 * t];
            r.x += x.x * wgt[s];
            r.y += x.y * wgt[s];
            r.z += x.z * wgt[s];
            r.w += x.w * wgt[s];
        }
        o[t] = r;
    }
}

// ---------------------------------------------------------------------------
extern "C" void kernel_launch(void* const* d_in, const int* in_sizes, int n_in,
                              void* d_out, int out_size)
{
    const float* blob = (const float*)d_in[0];
    const float* wq   = (const float*)d_in[1];
    const float* bq   = (const float*)d_in[2];
    const float* wk   = (const float*)d_in[3];
    const float* bk   = (const float*)d_in[4];
    const float* wv   = (const float*)d_in[5];
    const float* bv   = (const float*)d_in[6];
    float* out        = (float*)d_out;

    prep_all<<<608, 256>>>(blob, wq, wk, wv);
    proj_gemm<<<576, 256>>>(bq, bk, bv);
    attn_tc_kernel<<<dim3(8, NH, BB * SPLIT), 256>>>();
    combine_kernel<<<512, 256>>>(out);
}

// round 11
// speedup vs baseline: 8.3626x; 1.0022x over previous
#include <cuda_runtime.h>
#include <cuda_fp16.h>
#include <math.h>
#include <stdint.h>

// Problem constants
#define BB 4
#define HH 64
#define WW 64
#define DD 256
#define NH 8
#define DK 32
#define DV 32
#define HW 4096
#define P2 1024
#define SPLIT 4
#define KSPS 1024        // keys per split

// Scratch
__device__ __half g_a16[BB * HW * DD];           //  8 MB blob f16
__device__ __half g_p16[BB * P2 * DD];           //  2 MB pooled blob f16
__device__ __half g_w16[3 * DD * DD];            // weights f16 [mode][n][k]
__device__ __half g_q[BB * NH * P2 * DK];        //  2 MB [bn][p][k] (pre-scaled 1/sqrt(K)*log2e)
__device__ __half g_k[BB * NH * HW * DK];        //  8 MB [bn][i][k]
__device__ __half g_v[BB * NH * DV * HW];        //  8 MB [bn][d][i] TRANSPOSED
__device__ float  g_po[SPLIT][BB * NH * P2 * DV];// 16 MB unnormalized partial O
__device__ float  g_pm[SPLIT][BB * NH * P2];     // partial max (log2 domain)
__device__ float  g_pl[SPLIT][BB * NH * P2];     // partial sum

#define ONES_F16X2 0x3C003C00u

// ---------------------------------------------------------------------------
__device__ __forceinline__ float ex2f(float x) {
    float r;
    asm("ex2.approx.ftz.f32 %0, %1;" : "=f"(r) : "f"(x));
    return r;
}
__device__ __forceinline__ uint32_t h2ex2(uint32_t x) {
    uint32_t r;
    asm("ex2.approx.f16x2 %0, %1;" : "=r"(r) : "r"(x));
    return r;
}
__device__ __forceinline__ void mma_f16(float& d0, float& d1, float& d2, float& d3,
                                        uint32_t a0, uint32_t a1, uint32_t a2, uint32_t a3,
                                        uint32_t b0, uint32_t b1) {
    asm volatile(
        "mma.sync.aligned.m16n8k16.row.col.f32.f16.f16.f32 "
        "{%0,%1,%2,%3}, {%4,%5,%6,%7}, {%8,%9}, {%0,%1,%2,%3};\n"
        : "+f"(d0), "+f"(d1), "+f"(d2), "+f"(d3)
        : "r"(a0), "r"(a1), "r"(a2), "r"(a3), "r"(b0), "r"(b1));
}
__device__ __forceinline__ void ldsm_x4(uint32_t& r0, uint32_t& r1, uint32_t& r2, uint32_t& r3,
                                        uint32_t a) {
    asm volatile("ldmatrix.sync.aligned.m8n8.x4.shared.b16 {%0,%1,%2,%3}, [%4];\n"
                 : "=r"(r0), "=r"(r1), "=r"(r2), "=r"(r3) : "r"(a));
}
__device__ __forceinline__ uint32_t smem_u32(const void* p) {
    return (uint32_t)__cvta_generic_to_shared(p);
}
__device__ __forceinline__ void cpa16(uint32_t s, const void* g) {
    asm volatile("cp.async.ca.shared.global [%0], [%1], 16;\n" :: "r"(s), "l"(g));
}
__device__ __forceinline__ void cpa_commit() { asm volatile("cp.async.commit_group;\n"); }
template <int N>
__device__ __forceinline__ void cpa_wait() { asm volatile("cp.async.wait_group %0;\n" :: "n"(N)); }

// ---------------------------------------------------------------------------
// Prep (merged): blk [0,512): blob f32->f16 + 2x2 maxpool.
//                blk [512,608): weights f32 [k][n] -> f16 [mode][n][k].
// ---------------------------------------------------------------------------
__global__ __launch_bounds__(256)
void prep_all(const float* __restrict__ blob,
              const float* __restrict__ wq, const float* __restrict__ wk,
              const float* __restrict__ wv)
{
    if (blockIdx.x < 512) {
        const int idx = blockIdx.x * 256 + threadIdx.x;    // 131072 total
        const int pp  = idx >> 5;
        const int c8  = (idx & 31) << 3;
        const int b  = pp >> 10, l = pp & 1023, h2 = l >> 5, w2 = l & 31;
        const int pix = (b * HH + 2 * h2) * WW + 2 * w2;
        const float* p = blob + (size_t)pix * DD + c8;

        float mx[8];
#pragma unroll
        for (int j = 0; j < 8; j++) mx[j] = -INFINITY;
        const int offs[4] = {0, DD, WW * DD, WW * DD + DD};
#pragma unroll
        for (int q = 0; q < 4; q++) {
            float4 v0 = *(const float4*)(p + offs[q]);
            float4 v1 = *(const float4*)(p + offs[q] + 4);
            float vv[8] = {v0.x, v0.y, v0.z, v0.w, v1.x, v1.y, v1.z, v1.w};
            __half hh[8];
#pragma unroll
            for (int j = 0; j < 8; j++) {
                hh[j] = __float2half_rn(vv[j]);
                mx[j] = fmaxf(mx[j], vv[j]);
            }
            const int pixq = pix + ((q >> 1) ? WW : 0) + (q & 1);
            *(uint4*)(g_a16 + (size_t)pixq * DD + c8) = *(uint4*)hh;
        }
        __half hm[8];
#pragma unroll
        for (int j = 0; j < 8; j++) hm[j] = __float2half_rn(mx[j]);
        *(uint4*)(g_p16 + (size_t)pp * DD + c8) = *(uint4*)hm;
    } else {
        const int idx = (blockIdx.x - 512) * 256 + threadIdx.x;   // 24576 total
        const int m   = idx >> 13;
        const int r   = idx & 8191;
        const int n   = r >> 5;
        const int k0  = (r & 31) << 3;
        const float* Wm = (m == 0) ? wq : (m == 1) ? wk : wv;
        __half tmp[8];
#pragma unroll
        for (int j = 0; j < 8; j++)
            tmp[j] = __float2half_rn(Wm[(size_t)(k0 + j) * DD + n]);
        *(uint4*)(g_w16 + ((size_t)m * DD + n) * DD + k0) = *(uint4*)tmp;
    }
}

// ---------------------------------------------------------------------------
// f16 tensor-core projections: 576 blocks (unchanged).
// ---------------------------------------------------------------------------
__global__ __launch_bounds__(256, 2)
void proj_gemm(const float* __restrict__ bq, const float* __restrict__ bk,
               const float* __restrict__ bv)
{
    __shared__ __half As[2][128][40];
    __shared__ __half Ws[2][128][40];

    const int tid  = threadIdx.x;
    const int w    = tid >> 5;
    const int lane = tid & 31;
    const int g    = lane >> 2;
    const int tig  = lane & 3;
    const int rsel = lane & 7;
    const int quad = lane >> 3;
    const int mw   = w & 3;
    const int nw   = w >> 2;

    const int blk = blockIdx.x;
    int mode, mt, n0;
    if (blk < 64)       { mode = 0; mt = blk >> 1;          n0 = (blk & 1) << 7; }
    else if (blk < 320) { mode = 1; mt = (blk - 64) >> 1;   n0 = (blk & 1) << 7; }
    else                { mode = 2; mt = (blk - 320) >> 1;  n0 = (blk & 1) << 7; }
    const int m0 = mt << 7;

    const __half* Aptr = (mode == 0) ? g_p16 : g_a16;
    const __half* Wptr = g_w16 + (size_t)mode * DD * DD;
    const float*  bias = (mode == 0) ? bq : (mode == 1) ? bk : bv;

    auto stage = [&](int k0, int buf) {
#pragma unroll
        for (int t = 0; t < 2; t++) {
            const int i   = tid + 256 * t;
            const int row = i >> 2;
            const int c   = i & 3;
            cpa16(smem_u32(&As[buf][row][c * 8]), Aptr + (size_t)(m0 + row) * DD + k0 + c * 8);
            cpa16(smem_u32(&Ws[buf][row][c * 8]), Wptr + (size_t)(n0 + row) * DD + k0 + c * 8);
        }
    };

    float acc[2][8][4];
#pragma unroll
    for (int t = 0; t < 2; t++)
#pragma unroll
        for (int nt = 0; nt < 8; nt++)
#pragma unroll
            for (int j = 0; j < 4; j++) acc[t][nt][j] = 0.0f;

    stage(0, 0);
    cpa_commit();

    for (int ks = 0; ks < 8; ks++) {
        const int buf = ks & 1;
        if (ks + 1 < 8) {
            stage((ks + 1) * 32, buf ^ 1);
            cpa_commit();
            cpa_wait<1>();
        } else {
            cpa_wait<0>();
        }
        __syncthreads();

#pragma unroll
        for (int kc = 0; kc < 2; kc++) {
            uint32_t af[2][4];
#pragma unroll
            for (int t = 0; t < 2; t++) {
                const uint32_t addr = smem_u32(
                    &As[buf][mw * 32 + t * 16 + rsel + ((quad & 1) << 3)]
                            [kc * 16 + ((quad >> 1) << 3)]);
                ldsm_x4(af[t][0], af[t][1], af[t][2], af[t][3], addr);
            }
#pragma unroll
            for (int p = 0; p < 4; p++) {
                uint32_t b0, b1, b2, b3;
                const uint32_t addr = smem_u32(
                    &Ws[buf][nw * 64 + p * 16 + rsel + ((quad >> 1) << 3)]
                            [kc * 16 + ((quad & 1) << 3)]);
                ldsm_x4(b0, b1, b2, b3, addr);
#pragma unroll
                for (int t = 0; t < 2; t++) {
                    mma_f16(acc[t][2 * p][0], acc[t][2 * p][1], acc[t][2 * p][2], acc[t][2 * p][3],
                            af[t][0], af[t][1], af[t][2], af[t][3], b0, b1);
                    mma_f16(acc[t][2 * p + 1][0], acc[t][2 * p + 1][1], acc[t][2 * p + 1][2], acc[t][2 * p + 1][3],
                            af[t][0], af[t][1], af[t][2], af[t][3], b2, b3);
                }
            }
        }
        __syncthreads();
    }

    const float QSCL = 0.17677669529663687f * 1.4426950408889634f;
#pragma unroll
    for (int t = 0; t < 2; t++) {
#pragma unroll
        for (int nt = 0; nt < 8; nt++) {
#pragma unroll
            for (int half = 0; half < 2; half++) {
                const int r = m0 + mw * 32 + t * 16 + g + half * 8;
#pragma unroll
                for (int j = 0; j < 2; j++) {
                    const int c = n0 + nw * 64 + nt * 8 + 2 * tig + j;
                    float val   = acc[t][nt][half * 2 + j] + __ldg(bias + c);
                    const int n = c >> 5;
                    const int d = c & 31;
                    if (mode == 0) {
                        val *= QSCL;
                        const int b = r >> 10, p2 = r & 1023;
                        g_q[(((b * NH + n) * P2) + p2) * DK + d] = __float2half_rn(val);
                    } else if (mode == 1) {
                        const int b = r >> 12, ii = r & 4095;
                        g_k[(((b * NH + n) * HW) + ii) * DK + d] = __float2half_rn(val);
                    } else {
                        val = val / (1.0f + __expf(-val));
                        const int b = r >> 12, ii = r & 4095;
                        g_v[(((size_t)(b * NH + n) * DV) + d) * HW + ii] = __float2half_rn(val);
                    }
                }
            }
        }
    }
}

// ---------------------------------------------------------------------------
// Split-K fp16 flash attention (SPLIT=4 -> 1024 blocks, 16 tiles each).
// Block: 8 warps / 256 thr / 128 queries; 1024 keys; 64-key tiles.
// 3-stage cp.async pipeline (one barrier per tile); warp-uniform lazy max;
// row-sum l via ones-fragment MMA.
// ---------------------------------------------------------------------------
__global__ __launch_bounds__(256)
void attn_tc_kernel()
{
    __shared__ __half Qs[128][40];
    __shared__ __half Ks[3][64][40];
    __shared__ __half VsT[3][32][72];

    const int tid  = threadIdx.x;
    const int w    = tid >> 5;            // 0..7
    const int lane = tid & 31;
    const int g    = lane >> 2;
    const int tig  = lane & 3;
    const int rsel = lane & 7;
    const int quad = lane >> 3;

    const int qt = blockIdx.x;            // 0..7 (128 queries each)
    const int n  = blockIdx.y;
    const int z  = blockIdx.z;            // 0..15
    const int b  = z >> 2;
    const int s  = z & 3;                 // key split 0..3
    const int bn = b * NH + n;

    const __half* qglob = g_q + (size_t)(bn * P2 + qt * 128) * DK;
    const __half* kglob = g_k + ((size_t)bn * HW + s * KSPS) * DK;
    const __half* vglob = g_v + (size_t)bn * DV * HW + s * KSPS;

    // stage Q once: 128 rows x 64B = 512 x 16B
#pragma unroll
    for (int t = 0; t < 2; t++) {
        const int i   = tid + 256 * t;
        const int row = i >> 2;
        const int c   = i & 3;
        *(float4*)&Qs[row][c * 8] = *(const float4*)(qglob + row * DK + c * 8);
    }

    auto stage = [&](int j0, int buf) {
        {   // K: 64 rows x 64B = 256 chunks
            const int row = tid >> 2;
            const int c   = tid & 3;
            cpa16(smem_u32(&Ks[buf][row][c * 8]), kglob + (size_t)(j0 + row) * DK + c * 8);
        }
        {   // V^T: 32 rows x 128B = 256 chunks
            const int row = tid >> 3;
            const int c   = tid & 7;
            cpa16(smem_u32(&VsT[buf][row][c * 8]), vglob + (size_t)row * HW + j0 + c * 8);
        }
    };

    const int NT = KSPS / 64;             // 16
    stage(0, 0);   cpa_commit();
    stage(64, 1);  cpa_commit();
    __syncthreads();                      // Qs visible

    uint32_t Qf[2][4];
    const int r0 = w * 16 + g;
#pragma unroll
    for (int kc = 0; kc < 2; kc++) {
        Qf[kc][0] = *(const uint32_t*)&Qs[r0    ][kc * 16 + 2 * tig    ];
        Qf[kc][1] = *(const uint32_t*)&Qs[r0 + 8][kc * 16 + 2 * tig    ];
        Qf[kc][2] = *(const uint32_t*)&Qs[r0    ][kc * 16 + 2 * tig + 8];
        Qf[kc][3] = *(const uint32_t*)&Qs[r0 + 8][kc * 16 + 2 * tig + 8];
    }

    float m = -INFINITY;                  // warp-uniform running max (log2 domain)
    float lacc[4] = {0.0f, 0.0f, 0.0f, 0.0f};
    float oacc[4][4];
#pragma unroll
    for (int i = 0; i < 4; i++)
#pragma unroll
        for (int j = 0; j < 4; j++) oacc[i][j] = 0.0f;

    for (int it = 0; it < NT; it++) {
        const int buf = it % 3;
        if (it == NT - 1) cpa_wait<0>(); else cpa_wait<1>();
        __syncthreads();                  // one barrier per tile

        // ---- S = Q K^T ----
        float sacc[8][4];
#pragma unroll
        for (int nt = 0; nt < 8; nt++)
#pragma unroll
            for (int j = 0; j < 4; j++) sacc[nt][j] = 0.0f;

#pragma unroll
        for (int kc = 0; kc < 2; kc++) {
#pragma unroll
            for (int p = 0; p < 4; p++) {
                uint32_t b0, b1, b2, b3;
                const uint32_t addr = smem_u32(
                    &Ks[buf][p * 16 + rsel + ((quad >> 1) << 3)]
                            [kc * 16 + ((quad & 1) << 3)]);
                ldsm_x4(b0, b1, b2, b3, addr);
                mma_f16(sacc[2 * p][0], sacc[2 * p][1], sacc[2 * p][2], sacc[2 * p][3],
                        Qf[kc][0], Qf[kc][1], Qf[kc][2], Qf[kc][3], b0, b1);
                mma_f16(sacc[2 * p + 1][0], sacc[2 * p + 1][1], sacc[2 * p + 1][2], sacc[2 * p + 1][3],
                        Qf[kc][0], Qf[kc][1], Qf[kc][2], Qf[kc][3], b2, b3);
            }
        }

        // ---- warp-uniform lazy max ----
        float mx = -INFINITY;
#pragma unroll
        for (int nt = 0; nt < 8; nt++) {
            mx = fmaxf(mx, fmaxf(fmaxf(sacc[nt][0], sacc[nt][1]),
                                 fmaxf(sacc[nt][2], sacc[nt][3])));
        }
#pragma unroll
        for (int d = 16; d >= 1; d >>= 1)
            mx = fmaxf(mx, __shfl_xor_sync(0xffffffffu, mx, d));

        if (mx > m) {                     // warp-uniform branch; rare after warmup
            const float sc = ex2f(m - mx);   // 0 on first tile
            m = mx;
#pragma unroll
            for (int nt = 0; nt < 4; nt++) {
                oacc[nt][0] *= sc; oacc[nt][1] *= sc;
                oacc[nt][2] *= sc; oacc[nt][3] *= sc;
            }
            lacc[0] *= sc; lacc[1] *= sc; lacc[2] *= sc; lacc[3] *= sc;
        }

        // ---- P = 2^(S - m) in f16 ----
        uint32_t hlo[8], hhi[8];
#pragma unroll
        for (int nt = 0; nt < 8; nt++) {
            __half2 d0 = __floats2half2_rn(sacc[nt][0] - m, sacc[nt][1] - m);
            __half2 d1 = __floats2half2_rn(sacc[nt][2] - m, sacc[nt][3] - m);
            hlo[nt] = h2ex2(*(uint32_t*)&d0);
            hhi[nt] = h2ex2(*(uint32_t*)&d1);
        }

        // ---- O += P V ; l += P @ 1 ----
#pragma unroll
        for (int kc = 0; kc < 4; kc++) {
            const uint32_t a0 = hlo[2 * kc];
            const uint32_t a1 = hhi[2 * kc];
            const uint32_t a2 = hlo[2 * kc + 1];
            const uint32_t a3 = hhi[2 * kc + 1];
            mma_f16(lacc[0], lacc[1], lacc[2], lacc[3],
                    a0, a1, a2, a3, ONES_F16X2, ONES_F16X2);
#pragma unroll
            for (int p = 0; p < 2; p++) {
                uint32_t b0, b1, b2, b3;
                const uint32_t addr = smem_u32(
                    &VsT[buf][p * 16 + rsel + ((quad >> 1) << 3)]
                             [kc * 16 + ((quad & 1) << 3)]);
                ldsm_x4(b0, b1, b2, b3, addr);
                mma_f16(oacc[2 * p][0], oacc[2 * p][1], oacc[2 * p][2], oacc[2 * p][3],
                        a0, a1, a2, a3, b0, b1);
                mma_f16(oacc[2 * p + 1][0], oacc[2 * p + 1][1], oacc[2 * p + 1][2], oacc[2 * p + 1][3],
                        a0, a1, a2, a3, b2, b3);
            }
        }

        // stage tile it+2 into buffer (it+2)%3
        if (it + 2 < NT) {
            stage((it + 2) * 64, (it + 2) % 3);
            cpa_commit();
        }
    }

    // ---- write partials (unnormalized) ----
    const int q0   = qt * 128 + w * 16 + g;
    const int row0 = bn * P2 + q0;
    const int row1 = row0 + 8;
    if (tig == 0) {
        g_pm[s][row0] = m;   g_pl[s][row0] = lacc[0];
        g_pm[s][row1] = m;   g_pl[s][row1] = lacc[2];
    }
    float* po0 = &g_po[s][(size_t)row0 * DV];
    float* po1 = &g_po[s][(size_t)row1 * DV];
#pragma unroll
    for (int nt = 0; nt < 4; nt++) {
        *(float2*)(po0 + nt * 8 + 2 * tig) = make_float2(oacc[nt][0], oacc[nt][1]);
        *(float2*)(po1 + nt * 8 + 2 * tig) = make_float2(oacc[nt][2], oacc[nt][3]);
    }
}

// ---------------------------------------------------------------------------
// Combine the four key-splits and normalize (8 elems/thread, float4).
// ---------------------------------------------------------------------------
__global__ __launch_bounds__(256)
void combine_kernel(float* __restrict__ out)
{
    const int idx = blockIdx.x * 256 + threadIdx.x;    // 131072 total
    const int row = idx >> 2;                          // bn*P2 + p
    const int d0  = (idx & 3) << 3;

    float pm[SPLIT];
#pragma unroll
    for (int s = 0; s < SPLIT; s++) pm[s] = g_pm[s][row];
    float M = pm[0];
#pragma unroll
    for (int s = 1; s < SPLIT; s++) M = fmaxf(M, pm[s]);

    float wgt[SPLIT];
    float den = 0.0f;
#pragma unroll
    for (int s = 0; s < SPLIT; s++) {
        wgt[s] = ex2f(pm[s] - M);
        den += g_pl[s][row] * wgt[s];
    }
    const float inv = 1.0f / den;
#pragma unroll
    for (int s = 0; s < SPLIT; s++) wgt[s] *= inv;

    const int b = row >> 13;
    const int n = (row >> 10) & 7;
    const int p = row & 1023;
    float4* o = (float4*)(out + ((size_t)(b * P2 + p) * 256) + n * DV + d0);

#pragma unroll
    for (int t = 0; t < 2; t++) {
        float4 r = make_float4(0.0f, 0.0f, 0.0f, 0.0f);
#pragma unroll
        for (int s = 0; s < SPLIT; s++) {
            float4 x = *(const float4*)&g_po[s][(size_t)row * DV + d0 + 4 * t];
            r.x += x.x * wgt[s];
            r.y += x.y * wgt[s];
            r.z += x.z * wgt[s];
            r.w += x.w * wgt[s];
        }
        o[t] = r;
    }
}

// ---------------------------------------------------------------------------
extern "C" void kernel_launch(void* const* d_in, const int* in_sizes, int n_in,
                              void* d_out, int out_size)
{
    const float* blob = (const float*)d_in[0];
    const float* wq   = (const float*)d_in[1];
    const float* bq   = (const float*)d_in[2];
    const float* wk   = (const float*)d_in[3];
    const float* bk   = (const float*)d_in[4];
    const float* wv   = (const float*)d_in[5];
    const float* bv   = (const float*)d_in[6];
    float* out        = (float*)d_out;

    prep_all<<<608, 256>>>(blob, wq, wk, wv);
    proj_gemm<<<576, 256>>>(bq, bk, bv);
    attn_tc_kernel<<<dim3(8, NH, BB * SPLIT), 256>>>();
    combine_kernel<<<512, 256>>>(out);
}